// round 13
// baseline (speedup 1.0000x reference)
#include <cuda_runtime.h>
#include <math.h>
#include <stdint.h>

// Problem constants (fixed by setup_inputs)
#define BATCH 2
#define TSEQ  2048
#define DMOD  2048
#define NHEAD 16
#define DHEAD 128
#define MROWS (BATCH * TSEQ)        // 4096
#define QKVN  (3 * DMOD)            // 6144

// ---------------------------------------------------------------------------
// Scratch (static device globals; no runtime allocation)
// ---------------------------------------------------------------------------
__device__ float g_qkv[(size_t)MROWS * QKVN];
__device__ float g_q[(size_t)BATCH * NHEAD * TSEQ * DHEAD];
__device__ float g_k[(size_t)BATCH * NHEAD * TSEQ * DHEAD];
__device__ float g_v[(size_t)BATCH * NHEAD * TSEQ * DHEAD];
__device__ float g_o[(size_t)MROWS * DMOD];     // attn out, [B,T,D] layout
__device__ float g_g[(size_t)MROWS * DMOD];     // gated, K-PERMUTED row-major
// tf32-rounded, layout-transformed copies of inputs:
//   g_xr: [M][K] row-major, k permuted within 8-groups
//   g_w*r: [K/8][N][8] atoms, k permuted within atom
__device__ float g_xr[(size_t)MROWS * DMOD];
__device__ float g_wqkvr[(size_t)DMOD * QKVN];
__device__ float g_wgater[(size_t)DMOD * DMOD];
__device__ float g_woutr[(size_t)DMOD * DMOD];
// RoPE table: [t][j] -> (cos, sin), j = 0..63
__device__ float2 g_rope[(size_t)TSEQ * 64];

// ---------------------------------------------------------------------------
// Helpers
// ---------------------------------------------------------------------------
__device__ __forceinline__ uint32_t f2tf(float x) {
    uint32_t r;
    asm("cvt.rna.tf32.f32 %0, %1;" : "=r"(r) : "f"(x));
    return r;
}

// inverse of pos(k) = k<4 ? 2k : 2(k-4)+1
__device__ __forceinline__ int invp(int p) {
    return (p & 1) ? (p >> 1) + 4 : (p >> 1);
}

__device__ __forceinline__ void mma_tf32(float* c, const uint32_t* a, const uint32_t* b) {
    asm volatile(
        "mma.sync.aligned.m16n8k8.row.col.f32.tf32.tf32.f32 "
        "{%0,%1,%2,%3},{%4,%5,%6,%7},{%8,%9},{%0,%1,%2,%3};\n"
        : "+f"(c[0]), "+f"(c[1]), "+f"(c[2]), "+f"(c[3])
        : "r"(a[0]), "r"(a[1]), "r"(a[2]), "r"(a[3]), "r"(b[0]), "r"(b[1]));
}

__device__ __forceinline__ void cpa16(void* dst, const void* src) {
    uint32_t d = (uint32_t)__cvta_generic_to_shared(dst);
    asm volatile("cp.async.cg.shared.global [%0], [%1], 16;" :: "r"(d), "l"(src));
}
#define CP_COMMIT() asm volatile("cp.async.commit_group;")
#define CP_WAIT0()  asm volatile("cp.async.wait_group 0;")
#define CP_WAIT1()  asm volatile("cp.async.wait_group 1;")
#define CP_WAIT2()  asm volatile("cp.async.wait_group 2;")

// ---------------------------------------------------------------------------
// Fused pre-pass: tf32 round + layout transform of x, W_qkv, W_gate, W_out
// + RoPE table. One launch.
// ---------------------------------------------------------------------------
#define RN1 ((MROWS * DMOD) / 4)            // x      float4 count
#define RN2 ((DMOD * QKVN) / 4)             // W_qkv
#define RN3 ((DMOD * DMOD) / 4)             // W_gate / W_out
#define RNTOT (RN1 + RN2 + 2 * RN3)
#define RNR (TSEQ * 64)
#define RNALL (RNTOT + RNR)

__device__ __forceinline__ float4 round4(float a, float b, float c, float d) {
    return make_float4(__uint_as_float(f2tf(a)), __uint_as_float(f2tf(b)),
                       __uint_as_float(f2tf(c)), __uint_as_float(f2tf(d)));
}

__global__ void __launch_bounds__(256)
fused_round_kernel(const float* __restrict__ x,  float* __restrict__ xr,
                   const float* __restrict__ w1, float* __restrict__ w1r,
                   const float* __restrict__ w2, float* __restrict__ w2r,
                   const float* __restrict__ w3, float* __restrict__ w3r,
                   float2* __restrict__ rtab)
{
    int i = blockIdx.x * blockDim.x + threadIdx.x;
    if (i >= RNALL) return;
    if (i >= RNTOT) {
        int idx = i - RNTOT;
        int t = idx >> 6;
        int j = idx & 63;
        double freq = exp(-((double)j / 64.0) * 9.210340371976184);  // ln(1e4)
        double ang = (double)t * freq;
        double sd, cd;
        sincos(ang, &sd, &cd);
        rtab[idx] = make_float2((float)cd, (float)sd);
        return;
    }
    if (i < RN1) {
        // x -> xr: row-major [M][K=2048], k permuted within 8-groups
        int o = i * 4;                 // output linear float index
        int m  = o >> 11;
        int kk = o & 2047;
        int p0 = kk & 7;               // 0 or 4
        const float* s = x + ((size_t)m << 11) + (kk & ~7);
        float4 v = round4(s[invp(p0)], s[invp(p0 + 1)],
                          s[invp(p0 + 2)], s[invp(p0 + 3)]);
        ((float4*)xr)[i] = v;
        return;
    }
    // W -> atoms [K/8][N][8], k permuted within atom
    const float* w; float* wr; long off; int N;
    if (i < RN1 + RN2)              { w = w1; wr = w1r; off = i - RN1; N = QKVN; }
    else if (i < RN1 + RN2 + RN3)   { w = w2; wr = w2r; off = i - RN1 - RN2; N = DMOD; }
    else                            { w = w3; wr = w3r; off = i - RN1 - RN2 - RN3; N = DMOD; }
    long o = off * 4;                  // output linear float index
    int p0 = (int)(o & 7);             // 0 or 4
    long an = o >> 3;
    int n = (int)(an % N);
    long a = an / N;
    const float* s = w + (size_t)(a << 3) * N + n;
    float4 v = round4(s[(size_t)invp(p0) * N],     s[(size_t)invp(p0 + 1) * N],
                      s[(size_t)invp(p0 + 2) * N], s[(size_t)invp(p0 + 3) * N]);
    ((float4*)wr)[off] = v;
}

// ---------------------------------------------------------------------------
// tf32 GEMM: C[M,N] = A[M,K] @ B[K,N].
// A: row-major k-permuted; B: [K/8][N][8] atoms (k-permuted).
// BM=BN=128, BK=16, 3-stage cp.async ring, 256 threads, warp tile 32x64.
// Fragment loads are float2 (LDS.64) -> 24 LDS per warp-kstep (was 48).
// BATS=8 (16B-aligned cp.async); BKP=24 (conflict-free float2 A-frags).
// mode 0: plain store; mode 1: gate epilogue (C written k-permuted).
// ---------------------------------------------------------------------------
#define BM 128
#define BN 128
#define BK 16
#define BKP 24          // A row stride in smem floats (96B: bank-safe)
#define BATS 8          // B per-n stride in smem floats (32B: cp.async aligned)
#define GST 3           // stages

#define AS(s, r, c) Ash[(size_t)(s) * BM * BKP + (r) * BKP + (c)]
#define BS8(s, ik, n, p) Bsh[((size_t)((s) * 2 + (ik)) * BN + (n)) * BATS + (p)]

#define GEMM_SMEM_FLOATS (GST * BM * BKP + GST * 2 * BN * BATS)  // 9216+6144

__global__ void __launch_bounds__(256, 2)
mm_tf32_kernel(const float* __restrict__ A, const float* __restrict__ B,
               float* __restrict__ C, int M, int N, int K,
               int mode, const float* __restrict__ bias,
               const float* __restrict__ gateO)
{
    extern __shared__ float gsm[];
    float* Ash = gsm;
    float* Bsh = gsm + GST * BM * BKP;

    const int bx = blockIdx.x, by = blockIdx.y;
    const int tid = threadIdx.x;
    const int lane = tid & 31;
    const int warp = tid >> 5;
    const int wm = warp >> 1;
    const int wn = warp & 1;
    const int g  = lane >> 2;
    const int tg = lane & 3;

    const int aR0 = tid >> 2;
    const int aC  = (tid & 3) << 2;

    const float* Abase = A + (size_t)(by * BM) * K;
    const int nbase = bx * BN;

    float acc[2][8][4];
#pragma unroll
    for (int im = 0; im < 2; im++)
#pragma unroll
        for (int in = 0; in < 8; in++)
#pragma unroll
            for (int j = 0; j < 4; j++) acc[im][in][j] = 0.f;

    const int KT = K / BK;

    // loaders:
    // A: 128 rows x 16 floats (2 passes of 64 rows, 16B each)
    // B: 2 atoms x 128 n x 32B = 512 x 16B (2 passes of 256)
#pragma unroll
    for (int s = 0; s < 2; s++) {
        const int a0 = s * 2;   // k-atom base
#pragma unroll
        for (int p = 0; p < 2; p++) {
            int r = aR0 + p * 64;
            cpa16(&AS(s, r, aC), Abase + (size_t)r * K + a0 * 8 + aC);
        }
#pragma unroll
        for (int p = 0; p < 2; p++) {
            int idx = tid + p * 256;
            int ph  = idx & 1;
            int n   = (idx >> 1) & (BN - 1);
            int ika = idx >> 8;
            cpa16(&BS8(s, ika, n, ph * 4),
                  B + (((size_t)(a0 + ika) * N + nbase + n) << 3) + ph * 4);
        }
        CP_COMMIT();
    }

    for (int kt = 0; kt < KT; kt++) {
        const int cur = kt % GST;
        if (kt + 1 < KT) { CP_WAIT1(); } else { CP_WAIT0(); }
        __syncthreads();

        if (kt + 2 < KT) {
            const int nxt = (kt + 2) % GST;
            const int a0 = (kt + 2) * 2;
#pragma unroll
            for (int p = 0; p < 2; p++) {
                int r = aR0 + p * 64;
                cpa16(&AS(nxt, r, aC), Abase + (size_t)r * K + a0 * 8 + aC);
            }
#pragma unroll
            for (int p = 0; p < 2; p++) {
                int idx = tid + p * 256;
                int ph  = idx & 1;
                int n   = (idx >> 1) & (BN - 1);
                int ika = idx >> 8;
                cpa16(&BS8(nxt, ika, n, ph * 4),
                      B + (((size_t)(a0 + ika) * N + nbase + n) << 3) + ph * 4);
            }
            CP_COMMIT();
        }

#pragma unroll
        for (int ik = 0; ik < 2; ik++) {
            uint32_t afr[2][4];
#pragma unroll
            for (int im = 0; im < 2; im++) {
                int r = wm * 32 + im * 16 + g;
                int c = ik * 8 + 2 * tg;    // permuted: (k=tg, k=tg+4) adjacent
                float2 lo = *(const float2*)&AS(cur, r, c);
                float2 hi = *(const float2*)&AS(cur, r + 8, c);
                afr[im][0] = __float_as_uint(lo.x);
                afr[im][2] = __float_as_uint(lo.y);
                afr[im][1] = __float_as_uint(hi.x);
                afr[im][3] = __float_as_uint(hi.y);
            }
            uint32_t bfr[8][2];
#pragma unroll
            for (int in = 0; in < 8; in++) {
                int cc = wn * 64 + in * 8 + g;
                float2 bv = *(const float2*)&BS8(cur, ik, cc, 2 * tg);
                bfr[in][0] = __float_as_uint(bv.x);
                bfr[in][1] = __float_as_uint(bv.y);
            }
#pragma unroll
            for (int im = 0; im < 2; im++)
#pragma unroll
                for (int in = 0; in < 8; in++)
                    mma_tf32(acc[im][in], afr[im], bfr[in]);
        }
    }

    if (mode == 0) {
#pragma unroll
        for (int im = 0; im < 2; im++) {
            int r = by * BM + wm * 32 + im * 16 + g;
#pragma unroll
            for (int in = 0; in < 8; in++) {
                int c = bx * BN + wn * 64 + in * 8 + 2 * tg;
                *(float2*)(C + (size_t)r * N + c) =
                    make_float2(acc[im][in][0], acc[im][in][1]);
                *(float2*)(C + (size_t)(r + 8) * N + c) =
                    make_float2(acc[im][in][2], acc[im][in][3]);
            }
        }
    } else {
        // gate epilogue: C = g is the out-GEMM's A operand -> write K-PERMUTED.
        // true columns n0 = base+2tg, n1 = n0+1 map to atom positions p0, p0+2.
        const int p0 = (tg < 2) ? 4 * tg : 4 * tg - 7;
#pragma unroll
        for (int im = 0; im < 2; im++) {
            int r0 = by * BM + wm * 32 + im * 16 + g;
            int r1 = r0 + 8;
            float2 bv[8], go0[8], go1[8];
#pragma unroll
            for (int in = 0; in < 8; in++) {
                int c = bx * BN + wn * 64 + in * 8 + 2 * tg;
                bv[in]  = *(const float2*)(bias + c);
                go0[in] = *(const float2*)(gateO + (size_t)r0 * N + c);
                go1[in] = *(const float2*)(gateO + (size_t)r1 * N + c);
            }
#pragma unroll
            for (int in = 0; in < 8; in++) {
                int nb = bx * BN + wn * 64 + in * 8;   // atom-aligned base
                float s00 = 1.f / (1.f + __expf(-(acc[im][in][0] + bv[in].x)));
                float s01 = 1.f / (1.f + __expf(-(acc[im][in][1] + bv[in].y)));
                float s10 = 1.f / (1.f + __expf(-(acc[im][in][2] + bv[in].x)));
                float s11 = 1.f / (1.f + __expf(-(acc[im][in][3] + bv[in].y)));
                C[(size_t)r0 * N + nb + p0]     = __uint_as_float(f2tf(s00 * go0[in].x));
                C[(size_t)r0 * N + nb + p0 + 2] = __uint_as_float(f2tf(s01 * go0[in].y));
                C[(size_t)r1 * N + nb + p0]     = __uint_as_float(f2tf(s10 * go1[in].x));
                C[(size_t)r1 * N + nb + p0 + 2] = __uint_as_float(f2tf(s11 * go1[in].y));
            }
        }
    }
}

// ---------------------------------------------------------------------------
// RMSNorm + RoPE for q,k (plus v permute); outputs tf32-rounded.
// Q is pre-scaled by 1/sqrt(d). RoPE angles from precomputed table.
// ---------------------------------------------------------------------------
__global__ void __launch_bounds__(128)
norm_rope_kernel(const float* __restrict__ qkv,
                 const float2* __restrict__ rtab,
                 float* __restrict__ Qo, float* __restrict__ Ko,
                 float* __restrict__ Vo)
{
    const int rid = blockIdx.x;
    const int t  = rid & (TSEQ - 1);
    const int bh = rid >> 11;
    const int b  = bh >> 4;
    const int h  = bh & (NHEAD - 1);
    const int i  = threadIdx.x;

    const float* row = qkv + ((size_t)(b * TSEQ + t)) * QKVN + h * DHEAD;
    float qv = row[i];
    float kv = row[DMOD + i];
    float vv = row[2 * DMOD + i];

    float q2 = qv * qv, k2 = kv * kv;
#pragma unroll
    for (int o = 16; o; o >>= 1) {
        q2 += __shfl_xor_sync(0xffffffffu, q2, o);
        k2 += __shfl_xor_sync(0xffffffffu, k2, o);
    }
    __shared__ float rq[4], rk[4];
    if ((i & 31) == 0) { rq[i >> 5] = q2; rk[i >> 5] = k2; }
    __syncthreads();
    float ssq = rq[0] + rq[1] + rq[2] + rq[3];
    float ssk = rk[0] + rk[1] + rk[2] + rk[3];
    float rnq = rsqrtf(ssq * (1.f / DHEAD) + 1e-6f);
    float rnk = rsqrtf(ssk * (1.f / DHEAD) + 1e-6f);

    __shared__ float sq[DHEAD], sk[DHEAD];
    sq[i] = qv * rnq;
    sk[i] = kv * rnk;
    __syncthreads();

    const int j = i & 63;
    float2 cs = rtab[(size_t)t * 64 + j];
    float c = cs.x, s = cs.y;

    float oq, ok;
    if (i < 64) {
        oq = sq[i] * c - sq[i + 64] * s;
        ok = sk[i] * c - sk[i + 64] * s;
    } else {
        oq = sq[i - 64] * s + sq[i] * c;
        ok = sk[i - 64] * s + sk[i] * c;
    }
    const float qscale = 0.08838834764831845f;  // 1/sqrt(128), folded into Q
    size_t oidx = ((size_t)bh * TSEQ + t) * DHEAD + i;
    Qo[oidx] = __uint_as_float(f2tf(oq * qscale));
    Ko[oidx] = __uint_as_float(f2tf(ok));
    Vo[oidx] = __uint_as_float(f2tf(vv));
}

// ---------------------------------------------------------------------------
// Flash attention (causal), tf32 mma. Br=128, Bc=64, 256 threads (8 warps).
// K and V triple-buffered with a 2-tile prefetch window. Q staging overlays
// K buffers 0-1; P converted reg->reg via shfl. Scale pre-folded into Q.
// O is written in [B,T,D] layout (permute fused -> coalesced gate epilogue).
// ---------------------------------------------------------------------------
#define ABR 128
#define ABC 64
#define DP  132            // d + 4
#define KTF (ABR / ABC)    // 2 kv-tiles per q-tile
#define NBUF 3
#define TILEF (ABC * DP)   // 8448 floats per tile buffer
#define FSM_FLOATS (2 * NBUF * TILEF)   // 50688 floats = 202752 B

__global__ void __launch_bounds__(256, 1)
flash_mma_kernel(const float* __restrict__ Qg, const float* __restrict__ Kg,
                 const float* __restrict__ Vg, float* __restrict__ Og)
{
    extern __shared__ float fsm[];

    const int qt = (gridDim.x - 1) - blockIdx.x;   // heavy tiles first
    const int bh = blockIdx.y;
    const int tid  = threadIdx.x;
    const int lane = tid & 31;
    const int w    = tid >> 5;          // warp 0..7
    const int g    = lane >> 2;
    const int tg   = lane & 3;

    const float* Qb = Qg + (size_t)bh * TSEQ * DHEAD;
    const float* Kb = Kg + (size_t)bh * TSEQ * DHEAD;
    const float* Vb = Vg + (size_t)bh * TSEQ * DHEAD;

    const int ktmax = KTF * (qt + 1);

    // --- prologue: stage Q (128x128) into K buffers 0-1 region
#pragma unroll
    for (int p = 0; p < 16; p++) {
        int idx = tid + p * 256;
        int r = idx >> 5;
        int c = (idx & 31) << 2;
        cpa16(&fsm[r * DP + c], Qb + (size_t)(qt * ABR + r) * DHEAD + c);
    }
    CP_COMMIT();
    CP_WAIT0();
    __syncthreads();

    uint32_t qf[16][4];
    {
        int r = w * 16 + g;
#pragma unroll
        for (int ik = 0; ik < 16; ik++) {
            int c = ik * 8 + tg;
            qf[ik][0] = __float_as_uint(fsm[r * DP + c]);
            qf[ik][1] = __float_as_uint(fsm[(r + 8) * DP + c]);
            qf[ik][2] = __float_as_uint(fsm[r * DP + c + 4]);
            qf[ik][3] = __float_as_uint(fsm[(r + 8) * DP + c + 4]);
        }
    }
    __syncthreads();   // all warps done with Q before K(0)/K(1) overwrite it

    // prefetch tiles 0 and 1 (one group each: {K,V})
#pragma unroll
    for (int s = 0; s < 2; s++) {
        if (s < ktmax) {
            float* ks = fsm + s * TILEF;
            float* vs = fsm + (NBUF + s) * TILEF;
            const float* kp = Kb + (size_t)s * ABC * DHEAD;
            const float* vp = Vb + (size_t)s * ABC * DHEAD;
#pragma unroll
            for (int p = 0; p < 8; p++) {
                int idx = tid + p * 256;
                int r = idx >> 5;
                int c = (idx & 31) << 2;
                cpa16(&ks[r * DP + c], kp + (size_t)r * DHEAD + c);
                cpa16(&vs[r * DP + c], vp + (size_t)r * DHEAD + c);
            }
            CP_COMMIT();
        }
    }

    float oacc[16][4];
#pragma unroll
    for (int in = 0; in < 16; in++)
#pragma unroll
        for (int j = 0; j < 4; j++) oacc[in][j] = 0.f;
    float m_i[2] = {-INFINITY, -INFINITY};
    float l_i[2] = {0.f, 0.f};

    const int rlo = qt * ABR + w * 16 + g;

    for (int kt = 0; kt < ktmax; kt++) {
        if (kt + 2 < ktmax) {
            int s = (kt + 2) % NBUF;
            float* ks = fsm + s * TILEF;
            float* vs = fsm + (NBUF + s) * TILEF;
            const float* kp = Kb + (size_t)(kt + 2) * ABC * DHEAD;
            const float* vp = Vb + (size_t)(kt + 2) * ABC * DHEAD;
#pragma unroll
            for (int p = 0; p < 8; p++) {
                int idx = tid + p * 256;
                int r = idx >> 5;
                int c = (idx & 31) << 2;
                cpa16(&ks[r * DP + c], kp + (size_t)r * DHEAD + c);
                cpa16(&vs[r * DP + c], vp + (size_t)r * DHEAD + c);
            }
            CP_COMMIT();
            CP_WAIT2();
        } else if (kt + 1 < ktmax) {
            CP_WAIT1();
        } else {
            CP_WAIT0();
        }
        __syncthreads();

        const float* Ksc = fsm + (kt % NBUF) * TILEF;
        const float* Vsc = fsm + (NBUF + kt % NBUF) * TILEF;

        // S = Q @ K^T  (warp: 16 x 64; 8 n-atoms)
        float sacc[8][4];
#pragma unroll
        for (int in = 0; in < 8; in++)
#pragma unroll
            for (int j = 0; j < 4; j++) sacc[in][j] = 0.f;

#pragma unroll
        for (int ik = 0; ik < 16; ik++) {
#pragma unroll
            for (int in = 0; in < 8; in++) {
                uint32_t bf[2];
                int srow = in * 8 + g;
                int dcol = ik * 8 + tg;
                bf[0] = __float_as_uint(Ksc[srow * DP + dcol]);
                bf[1] = __float_as_uint(Ksc[srow * DP + dcol + 4]);
                mma_tf32(sacc[in], qf[ik], bf);
            }
        }

        // causal mask (band tiles only)
        if (kt >= KTF * qt) {
#pragma unroll
            for (int in = 0; in < 8; in++) {
                int cbase = kt * ABC + in * 8 + 2 * tg;
#pragma unroll
                for (int j = 0; j < 4; j++) {
                    int cg = cbase + (j & 1);
                    int rg = rlo + (j >> 1) * 8;
                    if (cg > rg) sacc[in][j] = -INFINITY;
                }
            }
        }

        // online softmax per owned row (rr=0: row g ; rr=1: row g+8)
        float alpha[2];
#pragma unroll
        for (int rr = 0; rr < 2; rr++) {
            float pm = -INFINITY;
#pragma unroll
            for (int in = 0; in < 8; in++) {
                pm = fmaxf(pm, sacc[in][2 * rr]);
                pm = fmaxf(pm, sacc[in][2 * rr + 1]);
            }
            pm = fmaxf(pm, __shfl_xor_sync(0xffffffffu, pm, 1));
            pm = fmaxf(pm, __shfl_xor_sync(0xffffffffu, pm, 2));
            float mnew = fmaxf(m_i[rr], pm);
            float ps = 0.f;
#pragma unroll
            for (int in = 0; in < 8; in++) {
                float e0 = __expf(sacc[in][2 * rr]     - mnew);
                float e1 = __expf(sacc[in][2 * rr + 1] - mnew);
                sacc[in][2 * rr] = e0;
                sacc[in][2 * rr + 1] = e1;
                ps += e0 + e1;
            }
            ps += __shfl_xor_sync(0xffffffffu, ps, 1);
            ps += __shfl_xor_sync(0xffffffffu, ps, 2);
            alpha[rr] = __expf(m_i[rr] - mnew);
            l_i[rr] = l_i[rr] * alpha[rr] + ps;
            m_i[rr] = mnew;
        }
#pragma unroll
        for (int in = 0; in < 16; in++) {
            oacc[in][0] *= alpha[0]; oacc[in][1] *= alpha[0];
            oacc[in][2] *= alpha[1]; oacc[in][3] *= alpha[1];
        }

        // O += P @ V  (P converted C-frag -> A-frag via shfl; raw fp32 bits)
#pragma unroll
        for (int ik = 0; ik < 8; ik++) {
            const int srcA = (lane & 28) | (tg >> 1);
            const int srcB = srcA + 2;
            const bool odd = (tg & 1) != 0;
            float e0 = __shfl_sync(0xffffffffu, sacc[ik][0], srcA);
            float e1 = __shfl_sync(0xffffffffu, sacc[ik][1], srcA);
            float e2 = __shfl_sync(0xffffffffu, sacc[ik][2], srcA);
            float e3 = __shfl_sync(0xffffffffu, sacc[ik][3], srcA);
            float f0 = __shfl_sync(0xffffffffu, sacc[ik][0], srcB);
            float f1 = __shfl_sync(0xffffffffu, sacc[ik][1], srcB);
            float f2 = __shfl_sync(0xffffffffu, sacc[ik][2], srcB);
            float f3 = __shfl_sync(0xffffffffu, sacc[ik][3], srcB);
            uint32_t af[4];
            af[0] = __float_as_uint(odd ? e1 : e0);   // P[g][tg]
            af[1] = __float_as_uint(odd ? e3 : e2);   // P[g+8][tg]
            af[2] = __float_as_uint(odd ? f1 : f0);   // P[g][tg+4]
            af[3] = __float_as_uint(odd ? f3 : f2);   // P[g+8][tg+4]
#pragma unroll
            for (int in = 0; in < 16; in++) {
                uint32_t bf[2];
                int krow = ik * 8 + tg;
                int dcol = in * 8 + g;
                bf[0] = __float_as_uint(Vsc[krow * DP + dcol]);
                bf[1] = __float_as_uint(Vsc[(krow + 4) * DP + dcol]);
                mma_tf32(oacc[in], af, bf);
            }
        }
        __syncthreads();   // all warps done with buffer kt%3 before refill
    }

    // epilogue: write O in [B,T,D] layout (fused permute)
    float inv0 = 1.f / l_i[0];
    float inv1 = 1.f / l_i[1];
    {
        const int b = bh >> 4;
        const int h = bh & (NHEAD - 1);
        const int t0 = qt * ABR + w * 16 + g;
        float* O0 = Og + ((size_t)(b * TSEQ + t0)     ) * DMOD + h * DHEAD;
        float* O1 = Og + ((size_t)(b * TSEQ + t0 + 8) ) * DMOD + h * DHEAD;
#pragma unroll
        for (int in = 0; in < 16; in++) {
            int c = in * 8 + 2 * tg;
            *(float2*)(O0 + c) =
                make_float2(oacc[in][0] * inv0, oacc[in][1] * inv0);
            *(float2*)(O1 + c) =
                make_float2(oacc[in][2] * inv1, oacc[in][3] * inv1);
        }
    }
}

// ---------------------------------------------------------------------------
// Host launcher
// ---------------------------------------------------------------------------
extern "C" void kernel_launch(void* const* d_in, const int* in_sizes, int n_in,
                              void* d_out, int out_size)
{
    const float* x     = (const float*)d_in[0];
    const float* Wqkv  = (const float*)d_in[1];
    const float* Wout  = (const float*)d_in[2];
    const float* Wgate = (const float*)d_in[3];
    const float* bgate = (const float*)d_in[4];
    float* out = (float*)d_out;

    float *qkv, *q, *k, *v, *o, *g, *xr, *wqkvr, *wgater, *woutr;
    float2* rtab;
    cudaGetSymbolAddress((void**)&qkv,    g_qkv);
    cudaGetSymbolAddress((void**)&q,      g_q);
    cudaGetSymbolAddress((void**)&k,      g_k);
    cudaGetSymbolAddress((void**)&v,      g_v);
    cudaGetSymbolAddress((void**)&o,      g_o);
    cudaGetSymbolAddress((void**)&g,      g_g);
    cudaGetSymbolAddress((void**)&xr,     g_xr);
    cudaGetSymbolAddress((void**)&wqkvr,  g_wqkvr);
    cudaGetSymbolAddress((void**)&wgater, g_wgater);
    cudaGetSymbolAddress((void**)&woutr,  g_woutr);
    cudaGetSymbolAddress((void**)&rtab,   g_rope);

    // 0) fused tf32 pre-round + layout transform + RoPE table (launch #1)
    fused_round_kernel<<<(RNALL + 255) / 256, 256>>>(
        x, xr, Wqkv, wqkvr, Wgate, wgater, Wout, woutr, rtab);

    size_t gemm_smem = (size_t)GEMM_SMEM_FLOATS * sizeof(float);
    cudaFuncSetAttribute(mm_tf32_kernel,
                         cudaFuncAttributeMaxDynamicSharedMemorySize, (int)gemm_smem);

    // 1) QKV GEMM (launch #2)
    mm_tf32_kernel<<<dim3(QKVN / BN, MROWS / BM), 256, gemm_smem>>>(
        xr, wqkvr, qkv, MROWS, QKVN, DMOD, 0, nullptr, nullptr);

    // 2) RMSNorm + RoPE + permute (launch #3)
    norm_rope_kernel<<<BATCH * NHEAD * TSEQ, 128>>>(qkv, rtab, q, k, v);

    // 3) Flash attention (launch #4 -> ncu target)
    size_t fl_smem = (size_t)FSM_FLOATS * sizeof(float);
    cudaFuncSetAttribute(flash_mma_kernel,
                         cudaFuncAttributeMaxDynamicSharedMemorySize, (int)fl_smem);
    flash_mma_kernel<<<dim3(TSEQ / ABR, BATCH * NHEAD), 256, fl_smem>>>(q, k, v, o);

    // 4) gate GEMM with fused sigmoid * attn epilogue (launch #5)
    mm_tf32_kernel<<<dim3(DMOD / BN, MROWS / BM), 256, gemm_smem>>>(
        xr, wgater, g, MROWS, DMOD, DMOD, 1, bgate, o);

    // 5) output GEMM (launch #6)
    mm_tf32_kernel<<<dim3(DMOD / BN, MROWS / BM), 256, gemm_smem>>>(
        g, woutr, out, MROWS, DMOD, DMOD, 0, nullptr, nullptr);
}

// round 14
// speedup vs baseline: 1.1097x; 1.1097x over previous
#include <cuda_runtime.h>
#include <math.h>
#include <stdint.h>

// Problem constants (fixed by setup_inputs)
#define BATCH 2
#define TSEQ  2048
#define DMOD  2048
#define NHEAD 16
#define DHEAD 128
#define MROWS (BATCH * TSEQ)        // 4096
#define QKVN  (3 * DMOD)            // 6144

// ---------------------------------------------------------------------------
// Scratch (static device globals; no runtime allocation)
// ---------------------------------------------------------------------------
__device__ float g_qkv[(size_t)MROWS * QKVN];
__device__ float g_q[(size_t)BATCH * NHEAD * TSEQ * DHEAD];
__device__ float g_k[(size_t)BATCH * NHEAD * TSEQ * DHEAD];
__device__ float g_v[(size_t)BATCH * NHEAD * TSEQ * DHEAD];
__device__ float g_o[(size_t)MROWS * DMOD];     // attn out, [B,T,D] layout
__device__ float g_g[(size_t)MROWS * DMOD];
// tf32-rounded copies of inputs (plain row-major, same layout as source)
__device__ float g_xr[(size_t)MROWS * DMOD];
__device__ float g_wqkvr[(size_t)DMOD * QKVN];
__device__ float g_wgater[(size_t)DMOD * DMOD];
__device__ float g_woutr[(size_t)DMOD * DMOD];
// RoPE table: [t][j] -> (cos, sin), j = 0..63
__device__ float2 g_rope[(size_t)TSEQ * 64];

// ---------------------------------------------------------------------------
// Helpers
// ---------------------------------------------------------------------------
__device__ __forceinline__ uint32_t f2tf(float x) {
    uint32_t r;
    asm("cvt.rna.tf32.f32 %0, %1;" : "=r"(r) : "f"(x));
    return r;
}

__device__ __forceinline__ void mma_tf32(float* c, const uint32_t* a, const uint32_t* b) {
    asm volatile(
        "mma.sync.aligned.m16n8k8.row.col.f32.tf32.tf32.f32 "
        "{%0,%1,%2,%3},{%4,%5,%6,%7},{%8,%9},{%0,%1,%2,%3};\n"
        : "+f"(c[0]), "+f"(c[1]), "+f"(c[2]), "+f"(c[3])
        : "r"(a[0]), "r"(a[1]), "r"(a[2]), "r"(a[3]), "r"(b[0]), "r"(b[1]));
}

__device__ __forceinline__ void cpa16(void* dst, const void* src) {
    uint32_t d = (uint32_t)__cvta_generic_to_shared(dst);
    asm volatile("cp.async.cg.shared.global [%0], [%1], 16;" :: "r"(d), "l"(src));
}
#define CP_COMMIT() asm volatile("cp.async.commit_group;")
#define CP_WAIT0()  asm volatile("cp.async.wait_group 0;")
#define CP_WAIT1()  asm volatile("cp.async.wait_group 1;")
#define CP_WAIT2()  asm volatile("cp.async.wait_group 2;")

// ---------------------------------------------------------------------------
// Pre-pass kernels (split into 3 launches so QKV GEMM lands at launch #4
// for ncu). Plain contiguous tf32 rounding, layouts unchanged.
// ---------------------------------------------------------------------------
#define RN1 ((MROWS * DMOD) / 4)    // x float4 count
#define RN2 ((DMOD * QKVN) / 4)     // W_qkv
#define RN3 ((DMOD * DMOD) / 4)     // W_gate / W_out
#define RNR (TSEQ * 64)             // rope entries

__device__ __forceinline__ void round_f4(const float4* src, float4* dst, int i) {
    float4 v = src[i];
    v.x = __uint_as_float(f2tf(v.x));
    v.y = __uint_as_float(f2tf(v.y));
    v.z = __uint_as_float(f2tf(v.z));
    v.w = __uint_as_float(f2tf(v.w));
    dst[i] = v;
}

// launch #1: round x + build rope table
__global__ void __launch_bounds__(256)
pre_x_rope_kernel(const float* __restrict__ x, float* __restrict__ xr,
                  float2* __restrict__ rtab)
{
    int i = blockIdx.x * blockDim.x + threadIdx.x;
    if (i < RN1) {
        round_f4((const float4*)x, (float4*)xr, i);
        return;
    }
    int idx = i - RN1;
    if (idx < RNR) {
        int t = idx >> 6;
        int j = idx & 63;
        double freq = exp(-((double)j / 64.0) * 9.210340371976184);  // ln(1e4)
        double ang = (double)t * freq;
        double sd, cd;
        sincos(ang, &sd, &cd);
        rtab[idx] = make_float2((float)cd, (float)sd);
    }
}

// launch #2: round W_qkv
__global__ void __launch_bounds__(256)
pre_wqkv_kernel(const float* __restrict__ w, float* __restrict__ wr)
{
    int i = blockIdx.x * blockDim.x + threadIdx.x;
    if (i < RN2) round_f4((const float4*)w, (float4*)wr, i);
}

// launch #3: round W_gate + W_out
__global__ void __launch_bounds__(256)
pre_wgo_kernel(const float* __restrict__ wg, float* __restrict__ wgr,
               const float* __restrict__ wo, float* __restrict__ wor)
{
    int i = blockIdx.x * blockDim.x + threadIdx.x;
    if (i < RN3)            round_f4((const float4*)wg, (float4*)wgr, i);
    else if (i < 2 * RN3)   round_f4((const float4*)wo, (float4*)wor, i - RN3);
}

// ---------------------------------------------------------------------------
// tf32 GEMM: C[M,N] = A[M,K] @ B[K,N] (A,B pre-rounded, row-major).
// BM=BN=128, BK=16, 3-stage cp.async ring, 128 threads (4 warps),
// warp tile 64x64 (warps 2x2) -> B-fragment reuse across 4 m-atoms:
// 32 LDS per 32 MMAs per warp-kstep (was 24 per 16).
// mode 0: plain store; mode 1: C = round(sigmoid(acc+bias[n]) * gateO[m,n])
// ---------------------------------------------------------------------------
#define BM 128
#define BN 128
#define BK 16
#define BKP (BK + 4)    // 20
#define BNP (BN + 8)    // 136
#define GST 3           // stages
#define GTHR 128        // threads

#define AS(s, r, c) Ash[(size_t)(s) * BM * BKP + (r) * BKP + (c)]
#define BS(s, r, c) Bsh[(size_t)(s) * BK * BNP + (r) * BNP + (c)]

#define GEMM_SMEM_FLOATS (GST * BM * BKP + GST * BK * BNP)   // 7680 + 6528

__global__ void __launch_bounds__(GTHR, 2)
mm_tf32_kernel(const float* __restrict__ A, const float* __restrict__ B,
               float* __restrict__ C, int M, int N, int K,
               int mode, const float* __restrict__ bias,
               const float* __restrict__ gateO)
{
    extern __shared__ float gsm[];
    float* Ash = gsm;
    float* Bsh = gsm + GST * BM * BKP;

    const int bx = blockIdx.x, by = blockIdx.y;
    const int tid = threadIdx.x;
    const int lane = tid & 31;
    const int warp = tid >> 5;          // 0..3
    const int wm = warp >> 1;           // 0..1 -> M offset wm*64
    const int wn = warp & 1;            // 0..1 -> N offset wn*64
    const int g  = lane >> 2;
    const int tg = lane & 3;

    const float* Abase = A + (size_t)(by * BM) * K;
    const float* Bbase = B + (size_t)(bx * BN);

    float acc[4][8][4];
#pragma unroll
    for (int im = 0; im < 4; im++)
#pragma unroll
        for (int in = 0; in < 8; in++)
#pragma unroll
            for (int j = 0; j < 4; j++) acc[im][in][j] = 0.f;

    const int KT = K / BK;

    // loaders (128 threads):
    // A: 128 rows x 16 floats = 512 float4 -> 4 per thread
    // B: 16 rows x 128 floats = 512 float4 -> 4 per thread
#pragma unroll
    for (int s = 0; s < 2; s++) {
        const int k0 = s * BK;
#pragma unroll
        for (int p = 0; p < 4; p++) {
            int idx = tid + p * GTHR;
            int r  = idx >> 2;
            int c4 = (idx & 3) << 2;
            cpa16(&AS(s, r, c4), Abase + (size_t)r * K + k0 + c4);
        }
#pragma unroll
        for (int p = 0; p < 4; p++) {
            int idx = tid + p * GTHR;
            int r  = idx >> 5;
            int c4 = (idx & 31) << 2;
            cpa16(&BS(s, r, c4), Bbase + (size_t)(k0 + r) * N + c4);
        }
        CP_COMMIT();
    }

    for (int kt = 0; kt < KT; kt++) {
        const int cur = kt % GST;
        if (kt + 1 < KT) { CP_WAIT1(); } else { CP_WAIT0(); }
        __syncthreads();

        if (kt + 2 < KT) {
            const int nxt = (kt + 2) % GST;
            const int k0 = (kt + 2) * BK;
#pragma unroll
            for (int p = 0; p < 4; p++) {
                int idx = tid + p * GTHR;
                int r  = idx >> 2;
                int c4 = (idx & 3) << 2;
                cpa16(&AS(nxt, r, c4), Abase + (size_t)r * K + k0 + c4);
            }
#pragma unroll
            for (int p = 0; p < 4; p++) {
                int idx = tid + p * GTHR;
                int r  = idx >> 5;
                int c4 = (idx & 31) << 2;
                cpa16(&BS(nxt, r, c4), Bbase + (size_t)(k0 + r) * N + c4);
            }
            CP_COMMIT();
        }

#pragma unroll
        for (int ik = 0; ik < 2; ik++) {
            uint32_t afr[4][4];
#pragma unroll
            for (int im = 0; im < 4; im++) {
                int r = wm * 64 + im * 16 + g;
                int c = ik * 8 + tg;
                afr[im][0] = __float_as_uint(AS(cur, r, c));
                afr[im][1] = __float_as_uint(AS(cur, r + 8, c));
                afr[im][2] = __float_as_uint(AS(cur, r, c + 4));
                afr[im][3] = __float_as_uint(AS(cur, r + 8, c + 4));
            }
            uint32_t bfr[8][2];
#pragma unroll
            for (int in = 0; in < 8; in++) {
                int cc = wn * 64 + in * 8 + g;
                int rk = ik * 8 + tg;
                bfr[in][0] = __float_as_uint(BS(cur, rk, cc));
                bfr[in][1] = __float_as_uint(BS(cur, rk + 4, cc));
            }
#pragma unroll
            for (int im = 0; im < 4; im++)
#pragma unroll
                for (int in = 0; in < 8; in++)
                    mma_tf32(acc[im][in], afr[im], bfr[in]);
        }
    }

    if (mode == 0) {
#pragma unroll
        for (int im = 0; im < 4; im++) {
            int r = by * BM + wm * 64 + im * 16 + g;
#pragma unroll
            for (int in = 0; in < 8; in++) {
                int c = bx * BN + wn * 64 + in * 8 + 2 * tg;
                *(float2*)(C + (size_t)r * N + c) =
                    make_float2(acc[im][in][0], acc[im][in][1]);
                *(float2*)(C + (size_t)(r + 8) * N + c) =
                    make_float2(acc[im][in][2], acc[im][in][3]);
            }
        }
    } else {
        // gateO in [B,T,D] -> index m*N + n, fully coalesced.
#pragma unroll
        for (int im = 0; im < 4; im++) {
            int r0 = by * BM + wm * 64 + im * 16 + g;
            int r1 = r0 + 8;
            float2 bv[8], go0[8], go1[8];
#pragma unroll
            for (int in = 0; in < 8; in++) {
                int c = bx * BN + wn * 64 + in * 8 + 2 * tg;
                bv[in]  = *(const float2*)(bias + c);
                go0[in] = *(const float2*)(gateO + (size_t)r0 * N + c);
                go1[in] = *(const float2*)(gateO + (size_t)r1 * N + c);
            }
#pragma unroll
            for (int in = 0; in < 8; in++) {
                int c = bx * BN + wn * 64 + in * 8 + 2 * tg;
                float s00 = 1.f / (1.f + __expf(-(acc[im][in][0] + bv[in].x)));
                float s01 = 1.f / (1.f + __expf(-(acc[im][in][1] + bv[in].y)));
                float s10 = 1.f / (1.f + __expf(-(acc[im][in][2] + bv[in].x)));
                float s11 = 1.f / (1.f + __expf(-(acc[im][in][3] + bv[in].y)));
                *(float2*)(C + (size_t)r0 * N + c) = make_float2(
                    __uint_as_float(f2tf(s00 * go0[in].x)),
                    __uint_as_float(f2tf(s01 * go0[in].y)));
                *(float2*)(C + (size_t)r1 * N + c) = make_float2(
                    __uint_as_float(f2tf(s10 * go1[in].x)),
                    __uint_as_float(f2tf(s11 * go1[in].y)));
            }
        }
    }
}

// ---------------------------------------------------------------------------
// RMSNorm + RoPE for q,k (plus v permute); outputs tf32-rounded.
// Q is pre-scaled by 1/sqrt(d). RoPE angles from precomputed table.
// ---------------------------------------------------------------------------
__global__ void __launch_bounds__(128)
norm_rope_kernel(const float* __restrict__ qkv,
                 const float2* __restrict__ rtab,
                 float* __restrict__ Qo, float* __restrict__ Ko,
                 float* __restrict__ Vo)
{
    const int rid = blockIdx.x;
    const int t  = rid & (TSEQ - 1);
    const int bh = rid >> 11;
    const int b  = bh >> 4;
    const int h  = bh & (NHEAD - 1);
    const int i  = threadIdx.x;

    const float* row = qkv + ((size_t)(b * TSEQ + t)) * QKVN + h * DHEAD;
    float qv = row[i];
    float kv = row[DMOD + i];
    float vv = row[2 * DMOD + i];

    float q2 = qv * qv, k2 = kv * kv;
#pragma unroll
    for (int o = 16; o; o >>= 1) {
        q2 += __shfl_xor_sync(0xffffffffu, q2, o);
        k2 += __shfl_xor_sync(0xffffffffu, k2, o);
    }
    __shared__ float rq[4], rk[4];
    if ((i & 31) == 0) { rq[i >> 5] = q2; rk[i >> 5] = k2; }
    __syncthreads();
    float ssq = rq[0] + rq[1] + rq[2] + rq[3];
    float ssk = rk[0] + rk[1] + rk[2] + rk[3];
    float rnq = rsqrtf(ssq * (1.f / DHEAD) + 1e-6f);
    float rnk = rsqrtf(ssk * (1.f / DHEAD) + 1e-6f);

    __shared__ float sq[DHEAD], sk[DHEAD];
    sq[i] = qv * rnq;
    sk[i] = kv * rnk;
    __syncthreads();

    const int j = i & 63;
    float2 cs = rtab[(size_t)t * 64 + j];
    float c = cs.x, s = cs.y;

    float oq, ok;
    if (i < 64) {
        oq = sq[i] * c - sq[i + 64] * s;
        ok = sk[i] * c - sk[i + 64] * s;
    } else {
        oq = sq[i - 64] * s + sq[i] * c;
        ok = sk[i - 64] * s + sk[i] * c;
    }
    const float qscale = 0.08838834764831845f;  // 1/sqrt(128), folded into Q
    size_t oidx = ((size_t)bh * TSEQ + t) * DHEAD + i;
    Qo[oidx] = __uint_as_float(f2tf(oq * qscale));
    Ko[oidx] = __uint_as_float(f2tf(ok));
    Vo[oidx] = __uint_as_float(f2tf(vv));
}

// ---------------------------------------------------------------------------
// Flash attention (causal), tf32 mma. Br=128, Bc=64, 256 threads (8 warps).
// K and V triple-buffered with a 2-tile prefetch window. Q staging overlays
// K buffers 0-1; P converted reg->reg via shfl. Scale pre-folded into Q.
// O is written in [B,T,D] layout (permute fused -> coalesced gate epilogue).
// ---------------------------------------------------------------------------
#define ABR 128
#define ABC 64
#define DP  132            // d + 4
#define KTF (ABR / ABC)    // 2 kv-tiles per q-tile
#define NBUF 3
#define TILEF (ABC * DP)   // 8448 floats per tile buffer
#define FSM_FLOATS (2 * NBUF * TILEF)   // 50688 floats = 202752 B

__global__ void __launch_bounds__(256, 1)
flash_mma_kernel(const float* __restrict__ Qg, const float* __restrict__ Kg,
                 const float* __restrict__ Vg, float* __restrict__ Og)
{
    extern __shared__ float fsm[];

    const int qt = (gridDim.x - 1) - blockIdx.x;   // heavy tiles first
    const int bh = blockIdx.y;
    const int tid  = threadIdx.x;
    const int lane = tid & 31;
    const int w    = tid >> 5;          // warp 0..7
    const int g    = lane >> 2;
    const int tg   = lane & 3;

    const float* Qb = Qg + (size_t)bh * TSEQ * DHEAD;
    const float* Kb = Kg + (size_t)bh * TSEQ * DHEAD;
    const float* Vb = Vg + (size_t)bh * TSEQ * DHEAD;

    const int ktmax = KTF * (qt + 1);

    // --- prologue: stage Q (128x128) into K buffers 0-1 region
#pragma unroll
    for (int p = 0; p < 16; p++) {
        int idx = tid + p * 256;
        int r = idx >> 5;
        int c = (idx & 31) << 2;
        cpa16(&fsm[r * DP + c], Qb + (size_t)(qt * ABR + r) * DHEAD + c);
    }
    CP_COMMIT();
    CP_WAIT0();
    __syncthreads();

    uint32_t qf[16][4];
    {
        int r = w * 16 + g;
#pragma unroll
        for (int ik = 0; ik < 16; ik++) {
            int c = ik * 8 + tg;
            qf[ik][0] = __float_as_uint(fsm[r * DP + c]);
            qf[ik][1] = __float_as_uint(fsm[(r + 8) * DP + c]);
            qf[ik][2] = __float_as_uint(fsm[r * DP + c + 4]);
            qf[ik][3] = __float_as_uint(fsm[(r + 8) * DP + c + 4]);
        }
    }
    __syncthreads();   // all warps done with Q before K(0)/K(1) overwrite it

    // prefetch tiles 0 and 1 (one group each: {K,V})
#pragma unroll
    for (int s = 0; s < 2; s++) {
        if (s < ktmax) {
            float* ks = fsm + s * TILEF;
            float* vs = fsm + (NBUF + s) * TILEF;
            const float* kp = Kb + (size_t)s * ABC * DHEAD;
            const float* vp = Vb + (size_t)s * ABC * DHEAD;
#pragma unroll
            for (int p = 0; p < 8; p++) {
                int idx = tid + p * 256;
                int r = idx >> 5;
                int c = (idx & 31) << 2;
                cpa16(&ks[r * DP + c], kp + (size_t)r * DHEAD + c);
                cpa16(&vs[r * DP + c], vp + (size_t)r * DHEAD + c);
            }
            CP_COMMIT();
        }
    }

    float oacc[16][4];
#pragma unroll
    for (int in = 0; in < 16; in++)
#pragma unroll
        for (int j = 0; j < 4; j++) oacc[in][j] = 0.f;
    float m_i[2] = {-INFINITY, -INFINITY};
    float l_i[2] = {0.f, 0.f};

    const int rlo = qt * ABR + w * 16 + g;

    for (int kt = 0; kt < ktmax; kt++) {
        if (kt + 2 < ktmax) {
            int s = (kt + 2) % NBUF;
            float* ks = fsm + s * TILEF;
            float* vs = fsm + (NBUF + s) * TILEF;
            const float* kp = Kb + (size_t)(kt + 2) * ABC * DHEAD;
            const float* vp = Vb + (size_t)(kt + 2) * ABC * DHEAD;
#pragma unroll
            for (int p = 0; p < 8; p++) {
                int idx = tid + p * 256;
                int r = idx >> 5;
                int c = (idx & 31) << 2;
                cpa16(&ks[r * DP + c], kp + (size_t)r * DHEAD + c);
                cpa16(&vs[r * DP + c], vp + (size_t)r * DHEAD + c);
            }
            CP_COMMIT();
            CP_WAIT2();
        } else if (kt + 1 < ktmax) {
            CP_WAIT1();
        } else {
            CP_WAIT0();
        }
        __syncthreads();

        const float* Ksc = fsm + (kt % NBUF) * TILEF;
        const float* Vsc = fsm + (NBUF + kt % NBUF) * TILEF;

        // S = Q @ K^T  (warp: 16 x 64; 8 n-atoms)
        float sacc[8][4];
#pragma unroll
        for (int in = 0; in < 8; in++)
#pragma unroll
            for (int j = 0; j < 4; j++) sacc[in][j] = 0.f;

#pragma unroll
        for (int ik = 0; ik < 16; ik++) {
#pragma unroll
            for (int in = 0; in < 8; in++) {
                uint32_t bf[2];
                int srow = in * 8 + g;
                int dcol = ik * 8 + tg;
                bf[0] = __float_as_uint(Ksc[srow * DP + dcol]);
                bf[1] = __float_as_uint(Ksc[srow * DP + dcol + 4]);
                mma_tf32(sacc[in], qf[ik], bf);
            }
        }

        // causal mask (band tiles only)
        if (kt >= KTF * qt) {
#pragma unroll
            for (int in = 0; in < 8; in++) {
                int cbase = kt * ABC + in * 8 + 2 * tg;
#pragma unroll
                for (int j = 0; j < 4; j++) {
                    int cg = cbase + (j & 1);
                    int rg = rlo + (j >> 1) * 8;
                    if (cg > rg) sacc[in][j] = -INFINITY;
                }
            }
        }

        // online softmax per owned row (rr=0: row g ; rr=1: row g+8)
        float alpha[2];
#pragma unroll
        for (int rr = 0; rr < 2; rr++) {
            float pm = -INFINITY;
#pragma unroll
            for (int in = 0; in < 8; in++) {
                pm = fmaxf(pm, sacc[in][2 * rr]);
                pm = fmaxf(pm, sacc[in][2 * rr + 1]);
            }
            pm = fmaxf(pm, __shfl_xor_sync(0xffffffffu, pm, 1));
            pm = fmaxf(pm, __shfl_xor_sync(0xffffffffu, pm, 2));
            float mnew = fmaxf(m_i[rr], pm);
            float ps = 0.f;
#pragma unroll
            for (int in = 0; in < 8; in++) {
                float e0 = __expf(sacc[in][2 * rr]     - mnew);
                float e1 = __expf(sacc[in][2 * rr + 1] - mnew);
                sacc[in][2 * rr] = e0;
                sacc[in][2 * rr + 1] = e1;
                ps += e0 + e1;
            }
            ps += __shfl_xor_sync(0xffffffffu, ps, 1);
            ps += __shfl_xor_sync(0xffffffffu, ps, 2);
            alpha[rr] = __expf(m_i[rr] - mnew);
            l_i[rr] = l_i[rr] * alpha[rr] + ps;
            m_i[rr] = mnew;
        }
#pragma unroll
        for (int in = 0; in < 16; in++) {
            oacc[in][0] *= alpha[0]; oacc[in][1] *= alpha[0];
            oacc[in][2] *= alpha[1]; oacc[in][3] *= alpha[1];
        }

        // O += P @ V  (P converted C-frag -> A-frag via shfl; raw fp32 bits)
#pragma unroll
        for (int ik = 0; ik < 8; ik++) {
            const int srcA = (lane & 28) | (tg >> 1);
            const int srcB = srcA + 2;
            const bool odd = (tg & 1) != 0;
            float e0 = __shfl_sync(0xffffffffu, sacc[ik][0], srcA);
            float e1 = __shfl_sync(0xffffffffu, sacc[ik][1], srcA);
            float e2 = __shfl_sync(0xffffffffu, sacc[ik][2], srcA);
            float e3 = __shfl_sync(0xffffffffu, sacc[ik][3], srcA);
            float f0 = __shfl_sync(0xffffffffu, sacc[ik][0], srcB);
            float f1 = __shfl_sync(0xffffffffu, sacc[ik][1], srcB);
            float f2 = __shfl_sync(0xffffffffu, sacc[ik][2], srcB);
            float f3 = __shfl_sync(0xffffffffu, sacc[ik][3], srcB);
            uint32_t af[4];
            af[0] = __float_as_uint(odd ? e1 : e0);   // P[g][tg]
            af[1] = __float_as_uint(odd ? e3 : e2);   // P[g+8][tg]
            af[2] = __float_as_uint(odd ? f1 : f0);   // P[g][tg+4]
            af[3] = __float_as_uint(odd ? f3 : f2);   // P[g+8][tg+4]
#pragma unroll
            for (int in = 0; in < 16; in++) {
                uint32_t bf[2];
                int krow = ik * 8 + tg;
                int dcol = in * 8 + g;
                bf[0] = __float_as_uint(Vsc[krow * DP + dcol]);
                bf[1] = __float_as_uint(Vsc[(krow + 4) * DP + dcol]);
                mma_tf32(oacc[in], af, bf);
            }
        }
        __syncthreads();   // all warps done with buffer kt%3 before refill
    }

    // epilogue: write O in [B,T,D] layout (fused permute)
    float inv0 = 1.f / l_i[0];
    float inv1 = 1.f / l_i[1];
    {
        const int b = bh >> 4;
        const int h = bh & (NHEAD - 1);
        const int t0 = qt * ABR + w * 16 + g;
        float* O0 = Og + ((size_t)(b * TSEQ + t0)     ) * DMOD + h * DHEAD;
        float* O1 = Og + ((size_t)(b * TSEQ + t0 + 8) ) * DMOD + h * DHEAD;
#pragma unroll
        for (int in = 0; in < 16; in++) {
            int c = in * 8 + 2 * tg;
            *(float2*)(O0 + c) =
                make_float2(oacc[in][0] * inv0, oacc[in][1] * inv0);
            *(float2*)(O1 + c) =
                make_float2(oacc[in][2] * inv1, oacc[in][3] * inv1);
        }
    }
}

// ---------------------------------------------------------------------------
// Host launcher
// ---------------------------------------------------------------------------
extern "C" void kernel_launch(void* const* d_in, const int* in_sizes, int n_in,
                              void* d_out, int out_size)
{
    const float* x     = (const float*)d_in[0];
    const float* Wqkv  = (const float*)d_in[1];
    const float* Wout  = (const float*)d_in[2];
    const float* Wgate = (const float*)d_in[3];
    const float* bgate = (const float*)d_in[4];
    float* out = (float*)d_out;

    float *qkv, *q, *k, *v, *o, *g, *xr, *wqkvr, *wgater, *woutr;
    float2* rtab;
    cudaGetSymbolAddress((void**)&qkv,    g_qkv);
    cudaGetSymbolAddress((void**)&q,      g_q);
    cudaGetSymbolAddress((void**)&k,      g_k);
    cudaGetSymbolAddress((void**)&v,      g_v);
    cudaGetSymbolAddress((void**)&o,      g_o);
    cudaGetSymbolAddress((void**)&g,      g_g);
    cudaGetSymbolAddress((void**)&xr,     g_xr);
    cudaGetSymbolAddress((void**)&wqkvr,  g_wqkvr);
    cudaGetSymbolAddress((void**)&wgater, g_wgater);
    cudaGetSymbolAddress((void**)&woutr,  g_woutr);
    cudaGetSymbolAddress((void**)&rtab,   g_rope);

    // 0) pre-pass (3 launches -> QKV GEMM is launch #4 for ncu)
    pre_x_rope_kernel<<<(RN1 + RNR + 255) / 256, 256>>>(x, xr, rtab);
    pre_wqkv_kernel<<<(RN2 + 255) / 256, 256>>>(Wqkv, wqkvr);
    pre_wgo_kernel<<<(2 * RN3 + 255) / 256, 256>>>(Wgate, wgater, Wout, woutr);

    size_t gemm_smem = (size_t)GEMM_SMEM_FLOATS * sizeof(float);
    cudaFuncSetAttribute(mm_tf32_kernel,
                         cudaFuncAttributeMaxDynamicSharedMemorySize, (int)gemm_smem);

    // 1) QKV GEMM (launch #4 -> ncu target)
    mm_tf32_kernel<<<dim3(QKVN / BN, MROWS / BM), GTHR, gemm_smem>>>(
        xr, wqkvr, qkv, MROWS, QKVN, DMOD, 0, nullptr, nullptr);

    // 2) RMSNorm + RoPE + permute (launch #5)
    norm_rope_kernel<<<BATCH * NHEAD * TSEQ, 128>>>(qkv, rtab, q, k, v);

    // 3) Flash attention (launch #6)
    size_t fl_smem = (size_t)FSM_FLOATS * sizeof(float);
    cudaFuncSetAttribute(flash_mma_kernel,
                         cudaFuncAttributeMaxDynamicSharedMemorySize, (int)fl_smem);
    flash_mma_kernel<<<dim3(TSEQ / ABR, BATCH * NHEAD), 256, fl_smem>>>(q, k, v, o);

    // 4) gate GEMM with fused sigmoid * attn epilogue (launch #7)
    mm_tf32_kernel<<<dim3(DMOD / BN, MROWS / BM), GTHR, gemm_smem>>>(
        xr, wgater, g, MROWS, DMOD, DMOD, 1, bgate, o);

    // 5) output GEMM (launch #8)
    mm_tf32_kernel<<<dim3(DMOD / BN, MROWS / BM), GTHR, gemm_smem>>>(
        g, woutr, out, MROWS, DMOD, DMOD, 0, nullptr, nullptr);
}

// round 15
// speedup vs baseline: 1.1172x; 1.0067x over previous
#include <cuda_runtime.h>
#include <math.h>
#include <stdint.h>

// Problem constants (fixed by setup_inputs)
#define BATCH 2
#define TSEQ  2048
#define DMOD  2048
#define NHEAD 16
#define DHEAD 128
#define MROWS (BATCH * TSEQ)        // 4096
#define QKVN  (3 * DMOD)            // 6144

// ---------------------------------------------------------------------------
// Scratch (static device globals; no runtime allocation)
// ---------------------------------------------------------------------------
__device__ float g_qkv[(size_t)MROWS * QKVN];
__device__ float g_q[(size_t)BATCH * NHEAD * TSEQ * DHEAD];
__device__ float g_k[(size_t)BATCH * NHEAD * TSEQ * DHEAD];
__device__ float g_v[(size_t)BATCH * NHEAD * TSEQ * DHEAD];
__device__ float g_o[(size_t)MROWS * DMOD];     // attn out, [B,T,D] layout
__device__ float g_g[(size_t)MROWS * DMOD];
// tf32-rounded copies of inputs (plain row-major, same layout as source)
__device__ float g_xr[(size_t)MROWS * DMOD];
__device__ float g_wqkvr[(size_t)DMOD * QKVN];
__device__ float g_wgater[(size_t)DMOD * DMOD];
__device__ float g_woutr[(size_t)DMOD * DMOD];
// RoPE table: [t][j] -> (cos, sin), j = 0..63
__device__ float2 g_rope[(size_t)TSEQ * 64];

// ---------------------------------------------------------------------------
// Helpers
// ---------------------------------------------------------------------------
__device__ __forceinline__ uint32_t f2tf(float x) {
    uint32_t r;
    asm("cvt.rna.tf32.f32 %0, %1;" : "=r"(r) : "f"(x));
    return r;
}

__device__ __forceinline__ void mma_tf32(float* c, const uint32_t* a, const uint32_t* b) {
    asm volatile(
        "mma.sync.aligned.m16n8k8.row.col.f32.tf32.tf32.f32 "
        "{%0,%1,%2,%3},{%4,%5,%6,%7},{%8,%9},{%0,%1,%2,%3};\n"
        : "+f"(c[0]), "+f"(c[1]), "+f"(c[2]), "+f"(c[3])
        : "r"(a[0]), "r"(a[1]), "r"(a[2]), "r"(a[3]), "r"(b[0]), "r"(b[1]));
}

__device__ __forceinline__ void cpa16(void* dst, const void* src) {
    uint32_t d = (uint32_t)__cvta_generic_to_shared(dst);
    asm volatile("cp.async.cg.shared.global [%0], [%1], 16;" :: "r"(d), "l"(src));
}
#define CP_COMMIT() asm volatile("cp.async.commit_group;")
#define CP_WAIT0()  asm volatile("cp.async.wait_group 0;")
#define CP_WAIT1()  asm volatile("cp.async.wait_group 1;")
#define CP_WAIT2()  asm volatile("cp.async.wait_group 2;")

// ---------------------------------------------------------------------------
// Pre-pass kernels (3 launches so QKV GEMM lands at launch #4 for ncu).
// ---------------------------------------------------------------------------
#define RN1 ((MROWS * DMOD) / 4)    // x float4 count
#define RN2 ((DMOD * QKVN) / 4)     // W_qkv
#define RN3 ((DMOD * DMOD) / 4)     // W_gate / W_out
#define RNR (TSEQ * 64)             // rope entries

__device__ __forceinline__ void round_f4(const float4* src, float4* dst, int i) {
    float4 v = src[i];
    v.x = __uint_as_float(f2tf(v.x));
    v.y = __uint_as_float(f2tf(v.y));
    v.z = __uint_as_float(f2tf(v.z));
    v.w = __uint_as_float(f2tf(v.w));
    dst[i] = v;
}

__global__ void __launch_bounds__(256)
pre_x_rope_kernel(const float* __restrict__ x, float* __restrict__ xr,
                  float2* __restrict__ rtab)
{
    int i = blockIdx.x * blockDim.x + threadIdx.x;
    if (i < RN1) {
        round_f4((const float4*)x, (float4*)xr, i);
        return;
    }
    int idx = i - RN1;
    if (idx < RNR) {
        int t = idx >> 6;
        int j = idx & 63;
        double freq = exp(-((double)j / 64.0) * 9.210340371976184);  // ln(1e4)
        double ang = (double)t * freq;
        double sd, cd;
        sincos(ang, &sd, &cd);
        rtab[idx] = make_float2((float)cd, (float)sd);
    }
}

__global__ void __launch_bounds__(256)
pre_wqkv_kernel(const float* __restrict__ w, float* __restrict__ wr)
{
    int i = blockIdx.x * blockDim.x + threadIdx.x;
    if (i < RN2) round_f4((const float4*)w, (float4*)wr, i);
}

__global__ void __launch_bounds__(256)
pre_wgo_kernel(const float* __restrict__ wg, float* __restrict__ wgr,
               const float* __restrict__ wo, float* __restrict__ wor)
{
    int i = blockIdx.x * blockDim.x + threadIdx.x;
    if (i < RN3)            round_f4((const float4*)wg, (float4*)wgr, i);
    else if (i < 2 * RN3)   round_f4((const float4*)wo, (float4*)wor, i - RN3);
}

// ---------------------------------------------------------------------------
// tf32 GEMM: C[M,N] = A[M,K] @ B[K,N] (A,B pre-rounded, row-major).
// BM=BN=128, BK=32, 3-stage cp.async ring, 128 threads (4 warps),
// warp tile 64x64 (warps 2x2). 4 k-steps per stage, half the barriers
// of BK=16; ptxas overlaps next-step fragment LDS with current MMAs.
// mode 0: plain store; mode 1: C = round(sigmoid(acc+bias[n]) * gateO[m,n])
// ---------------------------------------------------------------------------
#define BM 128
#define BN 128
#define BK 32
#define BKP (BK + 4)    // 36 (bank-safe: 36g mod 32 = 4g, distinct for g 0..7)
#define BNP (BN + 8)    // 136
#define GST 3           // stages
#define GTHR 128        // threads

#define AS(s, r, c) Ash[(size_t)(s) * BM * BKP + (r) * BKP + (c)]
#define BS(s, r, c) Bsh[(size_t)(s) * BK * BNP + (r) * BNP + (c)]

#define GEMM_SMEM_FLOATS (GST * BM * BKP + GST * BK * BNP)   // 13824 + 13056

__global__ void __launch_bounds__(GTHR, 2)
mm_tf32_kernel(const float* __restrict__ A, const float* __restrict__ B,
               float* __restrict__ C, int M, int N, int K,
               int mode, const float* __restrict__ bias,
               const float* __restrict__ gateO)
{
    extern __shared__ float gsm[];
    float* Ash = gsm;
    float* Bsh = gsm + GST * BM * BKP;

    const int bx = blockIdx.x, by = blockIdx.y;
    const int tid = threadIdx.x;
    const int lane = tid & 31;
    const int warp = tid >> 5;          // 0..3
    const int wm = warp >> 1;           // 0..1 -> M offset wm*64
    const int wn = warp & 1;            // 0..1 -> N offset wn*64
    const int g  = lane >> 2;
    const int tg = lane & 3;

    const float* Abase = A + (size_t)(by * BM) * K;
    const float* Bbase = B + (size_t)(bx * BN);

    float acc[4][8][4];
#pragma unroll
    for (int im = 0; im < 4; im++)
#pragma unroll
        for (int in = 0; in < 8; in++)
#pragma unroll
            for (int j = 0; j < 4; j++) acc[im][in][j] = 0.f;

    const int KT = K / BK;

    // loaders (128 threads):
    // A: 128 rows x 32 floats = 1024 float4 -> 8 per thread
    // B: 32 rows x 128 floats = 1024 float4 -> 8 per thread
#pragma unroll
    for (int s = 0; s < 2; s++) {
        const int k0 = s * BK;
#pragma unroll
        for (int p = 0; p < 8; p++) {
            int idx = tid + p * GTHR;
            int r  = idx >> 3;
            int c4 = (idx & 7) << 2;
            cpa16(&AS(s, r, c4), Abase + (size_t)r * K + k0 + c4);
        }
#pragma unroll
        for (int p = 0; p < 8; p++) {
            int idx = tid + p * GTHR;
            int r  = idx >> 5;
            int c4 = (idx & 31) << 2;
            cpa16(&BS(s, r, c4), Bbase + (size_t)(k0 + r) * N + c4);
        }
        CP_COMMIT();
    }

    for (int kt = 0; kt < KT; kt++) {
        const int cur = kt % GST;
        if (kt + 1 < KT) { CP_WAIT1(); } else { CP_WAIT0(); }
        __syncthreads();

        if (kt + 2 < KT) {
            const int nxt = (kt + 2) % GST;
            const int k0 = (kt + 2) * BK;
#pragma unroll
            for (int p = 0; p < 8; p++) {
                int idx = tid + p * GTHR;
                int r  = idx >> 3;
                int c4 = (idx & 7) << 2;
                cpa16(&AS(nxt, r, c4), Abase + (size_t)r * K + k0 + c4);
            }
#pragma unroll
            for (int p = 0; p < 8; p++) {
                int idx = tid + p * GTHR;
                int r  = idx >> 5;
                int c4 = (idx & 31) << 2;
                cpa16(&BS(nxt, r, c4), Bbase + (size_t)(k0 + r) * N + c4);
            }
            CP_COMMIT();
        }

#pragma unroll
        for (int ik = 0; ik < 4; ik++) {
            uint32_t afr[4][4];
#pragma unroll
            for (int im = 0; im < 4; im++) {
                int r = wm * 64 + im * 16 + g;
                int c = ik * 8 + tg;
                afr[im][0] = __float_as_uint(AS(cur, r, c));
                afr[im][1] = __float_as_uint(AS(cur, r + 8, c));
                afr[im][2] = __float_as_uint(AS(cur, r, c + 4));
                afr[im][3] = __float_as_uint(AS(cur, r + 8, c + 4));
            }
            uint32_t bfr[8][2];
#pragma unroll
            for (int in = 0; in < 8; in++) {
                int cc = wn * 64 + in * 8 + g;
                int rk = ik * 8 + tg;
                bfr[in][0] = __float_as_uint(BS(cur, rk, cc));
                bfr[in][1] = __float_as_uint(BS(cur, rk + 4, cc));
            }
#pragma unroll
            for (int im = 0; im < 4; im++)
#pragma unroll
                for (int in = 0; in < 8; in++)
                    mma_tf32(acc[im][in], afr[im], bfr[in]);
        }
    }

    if (mode == 0) {
#pragma unroll
        for (int im = 0; im < 4; im++) {
            int r = by * BM + wm * 64 + im * 16 + g;
#pragma unroll
            for (int in = 0; in < 8; in++) {
                int c = bx * BN + wn * 64 + in * 8 + 2 * tg;
                *(float2*)(C + (size_t)r * N + c) =
                    make_float2(acc[im][in][0], acc[im][in][1]);
                *(float2*)(C + (size_t)(r + 8) * N + c) =
                    make_float2(acc[im][in][2], acc[im][in][3]);
            }
        }
    } else {
        // gateO in [B,T,D] -> index m*N + n, fully coalesced.
#pragma unroll
        for (int im = 0; im < 4; im++) {
            int r0 = by * BM + wm * 64 + im * 16 + g;
            int r1 = r0 + 8;
            float2 bv[8], go0[8], go1[8];
#pragma unroll
            for (int in = 0; in < 8; in++) {
                int c = bx * BN + wn * 64 + in * 8 + 2 * tg;
                bv[in]  = *(const float2*)(bias + c);
                go0[in] = *(const float2*)(gateO + (size_t)r0 * N + c);
                go1[in] = *(const float2*)(gateO + (size_t)r1 * N + c);
            }
#pragma unroll
            for (int in = 0; in < 8; in++) {
                int c = bx * BN + wn * 64 + in * 8 + 2 * tg;
                float s00 = 1.f / (1.f + __expf(-(acc[im][in][0] + bv[in].x)));
                float s01 = 1.f / (1.f + __expf(-(acc[im][in][1] + bv[in].y)));
                float s10 = 1.f / (1.f + __expf(-(acc[im][in][2] + bv[in].x)));
                float s11 = 1.f / (1.f + __expf(-(acc[im][in][3] + bv[in].y)));
                *(float2*)(C + (size_t)r0 * N + c) = make_float2(
                    __uint_as_float(f2tf(s00 * go0[in].x)),
                    __uint_as_float(f2tf(s01 * go0[in].y)));
                *(float2*)(C + (size_t)r1 * N + c) = make_float2(
                    __uint_as_float(f2tf(s10 * go1[in].x)),
                    __uint_as_float(f2tf(s11 * go1[in].y)));
            }
        }
    }
}

// ---------------------------------------------------------------------------
// RMSNorm + RoPE for q,k (plus v permute); outputs tf32-rounded.
// Q is pre-scaled by 1/sqrt(d). RoPE angles from precomputed table.
// ---------------------------------------------------------------------------
__global__ void __launch_bounds__(128)
norm_rope_kernel(const float* __restrict__ qkv,
                 const float2* __restrict__ rtab,
                 float* __restrict__ Qo, float* __restrict__ Ko,
                 float* __restrict__ Vo)
{
    const int rid = blockIdx.x;
    const int t  = rid & (TSEQ - 1);
    const int bh = rid >> 11;
    const int b  = bh >> 4;
    const int h  = bh & (NHEAD - 1);
    const int i  = threadIdx.x;

    const float* row = qkv + ((size_t)(b * TSEQ + t)) * QKVN + h * DHEAD;
    float qv = row[i];
    float kv = row[DMOD + i];
    float vv = row[2 * DMOD + i];

    float q2 = qv * qv, k2 = kv * kv;
#pragma unroll
    for (int o = 16; o; o >>= 1) {
        q2 += __shfl_xor_sync(0xffffffffu, q2, o);
        k2 += __shfl_xor_sync(0xffffffffu, k2, o);
    }
    __shared__ float rq[4], rk[4];
    if ((i & 31) == 0) { rq[i >> 5] = q2; rk[i >> 5] = k2; }
    __syncthreads();
    float ssq = rq[0] + rq[1] + rq[2] + rq[3];
    float ssk = rk[0] + rk[1] + rk[2] + rk[3];
    float rnq = rsqrtf(ssq * (1.f / DHEAD) + 1e-6f);
    float rnk = rsqrtf(ssk * (1.f / DHEAD) + 1e-6f);

    __shared__ float sq[DHEAD], sk[DHEAD];
    sq[i] = qv * rnq;
    sk[i] = kv * rnk;
    __syncthreads();

    const int j = i & 63;
    float2 cs = rtab[(size_t)t * 64 + j];
    float c = cs.x, s = cs.y;

    float oq, ok;
    if (i < 64) {
        oq = sq[i] * c - sq[i + 64] * s;
        ok = sk[i] * c - sk[i + 64] * s;
    } else {
        oq = sq[i - 64] * s + sq[i] * c;
        ok = sk[i - 64] * s + sk[i] * c;
    }
    const float qscale = 0.08838834764831845f;  // 1/sqrt(128), folded into Q
    size_t oidx = ((size_t)bh * TSEQ + t) * DHEAD + i;
    Qo[oidx] = __uint_as_float(f2tf(oq * qscale));
    Ko[oidx] = __uint_as_float(f2tf(ok));
    Vo[oidx] = __uint_as_float(f2tf(vv));
}

// ---------------------------------------------------------------------------
// Flash attention (causal), tf32 mma. Br=128, Bc=64, 256 threads (8 warps).
// K and V triple-buffered with a 2-tile prefetch window. Q staging overlays
// K buffers 0-1; P converted reg->reg via shfl. Scale pre-folded into Q.
// O is written in [B,T,D] layout (permute fused -> coalesced gate epilogue).
// ---------------------------------------------------------------------------
#define ABR 128
#define ABC 64
#define DP  132            // d + 4
#define KTF (ABR / ABC)    // 2 kv-tiles per q-tile
#define NBUF 3
#define TILEF (ABC * DP)   // 8448 floats per tile buffer
#define FSM_FLOATS (2 * NBUF * TILEF)   // 50688 floats = 202752 B

__global__ void __launch_bounds__(256, 1)
flash_mma_kernel(const float* __restrict__ Qg, const float* __restrict__ Kg,
                 const float* __restrict__ Vg, float* __restrict__ Og)
{
    extern __shared__ float fsm[];

    const int qt = (gridDim.x - 1) - blockIdx.x;   // heavy tiles first
    const int bh = blockIdx.y;
    const int tid  = threadIdx.x;
    const int lane = tid & 31;
    const int w    = tid >> 5;          // warp 0..7
    const int g    = lane >> 2;
    const int tg   = lane & 3;

    const float* Qb = Qg + (size_t)bh * TSEQ * DHEAD;
    const float* Kb = Kg + (size_t)bh * TSEQ * DHEAD;
    const float* Vb = Vg + (size_t)bh * TSEQ * DHEAD;

    const int ktmax = KTF * (qt + 1);

    // --- prologue: stage Q (128x128) into K buffers 0-1 region
#pragma unroll
    for (int p = 0; p < 16; p++) {
        int idx = tid + p * 256;
        int r = idx >> 5;
        int c = (idx & 31) << 2;
        cpa16(&fsm[r * DP + c], Qb + (size_t)(qt * ABR + r) * DHEAD + c);
    }
    CP_COMMIT();
    CP_WAIT0();
    __syncthreads();

    uint32_t qf[16][4];
    {
        int r = w * 16 + g;
#pragma unroll
        for (int ik = 0; ik < 16; ik++) {
            int c = ik * 8 + tg;
            qf[ik][0] = __float_as_uint(fsm[r * DP + c]);
            qf[ik][1] = __float_as_uint(fsm[(r + 8) * DP + c]);
            qf[ik][2] = __float_as_uint(fsm[r * DP + c + 4]);
            qf[ik][3] = __float_as_uint(fsm[(r + 8) * DP + c + 4]);
        }
    }
    __syncthreads();   // all warps done with Q before K(0)/K(1) overwrite it

    // prefetch tiles 0 and 1 (one group each: {K,V})
#pragma unroll
    for (int s = 0; s < 2; s++) {
        if (s < ktmax) {
            float* ks = fsm + s * TILEF;
            float* vs = fsm + (NBUF + s) * TILEF;
            const float* kp = Kb + (size_t)s * ABC * DHEAD;
            const float* vp = Vb + (size_t)s * ABC * DHEAD;
#pragma unroll
            for (int p = 0; p < 8; p++) {
                int idx = tid + p * 256;
                int r = idx >> 5;
                int c = (idx & 31) << 2;
                cpa16(&ks[r * DP + c], kp + (size_t)r * DHEAD + c);
                cpa16(&vs[r * DP + c], vp + (size_t)r * DHEAD + c);
            }
            CP_COMMIT();
        }
    }

    float oacc[16][4];
#pragma unroll
    for (int in = 0; in < 16; in++)
#pragma unroll
        for (int j = 0; j < 4; j++) oacc[in][j] = 0.f;
    float m_i[2] = {-INFINITY, -INFINITY};
    float l_i[2] = {0.f, 0.f};

    const int rlo = qt * ABR + w * 16 + g;

    for (int kt = 0; kt < ktmax; kt++) {
        if (kt + 2 < ktmax) {
            int s = (kt + 2) % NBUF;
            float* ks = fsm + s * TILEF;
            float* vs = fsm + (NBUF + s) * TILEF;
            const float* kp = Kb + (size_t)(kt + 2) * ABC * DHEAD;
            const float* vp = Vb + (size_t)(kt + 2) * ABC * DHEAD;
#pragma unroll
            for (int p = 0; p < 8; p++) {
                int idx = tid + p * 256;
                int r = idx >> 5;
                int c = (idx & 31) << 2;
                cpa16(&ks[r * DP + c], kp + (size_t)r * DHEAD + c);
                cpa16(&vs[r * DP + c], vp + (size_t)r * DHEAD + c);
            }
            CP_COMMIT();
            CP_WAIT2();
        } else if (kt + 1 < ktmax) {
            CP_WAIT1();
        } else {
            CP_WAIT0();
        }
        __syncthreads();

        const float* Ksc = fsm + (kt % NBUF) * TILEF;
        const float* Vsc = fsm + (NBUF + kt % NBUF) * TILEF;

        // S = Q @ K^T  (warp: 16 x 64; 8 n-atoms)
        float sacc[8][4];
#pragma unroll
        for (int in = 0; in < 8; in++)
#pragma unroll
            for (int j = 0; j < 4; j++) sacc[in][j] = 0.f;

#pragma unroll
        for (int ik = 0; ik < 16; ik++) {
#pragma unroll
            for (int in = 0; in < 8; in++) {
                uint32_t bf[2];
                int srow = in * 8 + g;
                int dcol = ik * 8 + tg;
                bf[0] = __float_as_uint(Ksc[srow * DP + dcol]);
                bf[1] = __float_as_uint(Ksc[srow * DP + dcol + 4]);
                mma_tf32(sacc[in], qf[ik], bf);
            }
        }

        // causal mask (band tiles only)
        if (kt >= KTF * qt) {
#pragma unroll
            for (int in = 0; in < 8; in++) {
                int cbase = kt * ABC + in * 8 + 2 * tg;
#pragma unroll
                for (int j = 0; j < 4; j++) {
                    int cg = cbase + (j & 1);
                    int rg = rlo + (j >> 1) * 8;
                    if (cg > rg) sacc[in][j] = -INFINITY;
                }
            }
        }

        // online softmax per owned row (rr=0: row g ; rr=1: row g+8)
        float alpha[2];
#pragma unroll
        for (int rr = 0; rr < 2; rr++) {
            float pm = -INFINITY;
#pragma unroll
            for (int in = 0; in < 8; in++) {
                pm = fmaxf(pm, sacc[in][2 * rr]);
                pm = fmaxf(pm, sacc[in][2 * rr + 1]);
            }
            pm = fmaxf(pm, __shfl_xor_sync(0xffffffffu, pm, 1));
            pm = fmaxf(pm, __shfl_xor_sync(0xffffffffu, pm, 2));
            float mnew = fmaxf(m_i[rr], pm);
            float ps = 0.f;
#pragma unroll
            for (int in = 0; in < 8; in++) {
                float e0 = __expf(sacc[in][2 * rr]     - mnew);
                float e1 = __expf(sacc[in][2 * rr + 1] - mnew);
                sacc[in][2 * rr] = e0;
                sacc[in][2 * rr + 1] = e1;
                ps += e0 + e1;
            }
            ps += __shfl_xor_sync(0xffffffffu, ps, 1);
            ps += __shfl_xor_sync(0xffffffffu, ps, 2);
            alpha[rr] = __expf(m_i[rr] - mnew);
            l_i[rr] = l_i[rr] * alpha[rr] + ps;
            m_i[rr] = mnew;
        }
#pragma unroll
        for (int in = 0; in < 16; in++) {
            oacc[in][0] *= alpha[0]; oacc[in][1] *= alpha[0];
            oacc[in][2] *= alpha[1]; oacc[in][3] *= alpha[1];
        }

        // O += P @ V  (P converted C-frag -> A-frag via shfl; raw fp32 bits)
#pragma unroll
        for (int ik = 0; ik < 8; ik++) {
            const int srcA = (lane & 28) | (tg >> 1);
            const int srcB = srcA + 2;
            const bool odd = (tg & 1) != 0;
            float e0 = __shfl_sync(0xffffffffu, sacc[ik][0], srcA);
            float e1 = __shfl_sync(0xffffffffu, sacc[ik][1], srcA);
            float e2 = __shfl_sync(0xffffffffu, sacc[ik][2], srcA);
            float e3 = __shfl_sync(0xffffffffu, sacc[ik][3], srcA);
            float f0 = __shfl_sync(0xffffffffu, sacc[ik][0], srcB);
            float f1 = __shfl_sync(0xffffffffu, sacc[ik][1], srcB);
            float f2 = __shfl_sync(0xffffffffu, sacc[ik][2], srcB);
            float f3 = __shfl_sync(0xffffffffu, sacc[ik][3], srcB);
            uint32_t af[4];
            af[0] = __float_as_uint(odd ? e1 : e0);   // P[g][tg]
            af[1] = __float_as_uint(odd ? e3 : e2);   // P[g+8][tg]
            af[2] = __float_as_uint(odd ? f1 : f0);   // P[g][tg+4]
            af[3] = __float_as_uint(odd ? f3 : f2);   // P[g+8][tg+4]
#pragma unroll
            for (int in = 0; in < 16; in++) {
                uint32_t bf[2];
                int krow = ik * 8 + tg;
                int dcol = in * 8 + g;
                bf[0] = __float_as_uint(Vsc[krow * DP + dcol]);
                bf[1] = __float_as_uint(Vsc[(krow + 4) * DP + dcol]);
                mma_tf32(oacc[in], af, bf);
            }
        }
        __syncthreads();   // all warps done with buffer kt%3 before refill
    }

    // epilogue: write O in [B,T,D] layout (fused permute)
    float inv0 = 1.f / l_i[0];
    float inv1 = 1.f / l_i[1];
    {
        const int b = bh >> 4;
        const int h = bh & (NHEAD - 1);
        const int t0 = qt * ABR + w * 16 + g;
        float* O0 = Og + ((size_t)(b * TSEQ + t0)     ) * DMOD + h * DHEAD;
        float* O1 = Og + ((size_t)(b * TSEQ + t0 + 8) ) * DMOD + h * DHEAD;
#pragma unroll
        for (int in = 0; in < 16; in++) {
            int c = in * 8 + 2 * tg;
            *(float2*)(O0 + c) =
                make_float2(oacc[in][0] * inv0, oacc[in][1] * inv0);
            *(float2*)(O1 + c) =
                make_float2(oacc[in][2] * inv1, oacc[in][3] * inv1);
        }
    }
}

// ---------------------------------------------------------------------------
// Host launcher
// ---------------------------------------------------------------------------
extern "C" void kernel_launch(void* const* d_in, const int* in_sizes, int n_in,
                              void* d_out, int out_size)
{
    const float* x     = (const float*)d_in[0];
    const float* Wqkv  = (const float*)d_in[1];
    const float* Wout  = (const float*)d_in[2];
    const float* Wgate = (const float*)d_in[3];
    const float* bgate = (const float*)d_in[4];
    float* out = (float*)d_out;

    float *qkv, *q, *k, *v, *o, *g, *xr, *wqkvr, *wgater, *woutr;
    float2* rtab;
    cudaGetSymbolAddress((void**)&qkv,    g_qkv);
    cudaGetSymbolAddress((void**)&q,      g_q);
    cudaGetSymbolAddress((void**)&k,      g_k);
    cudaGetSymbolAddress((void**)&v,      g_v);
    cudaGetSymbolAddress((void**)&o,      g_o);
    cudaGetSymbolAddress((void**)&g,      g_g);
    cudaGetSymbolAddress((void**)&xr,     g_xr);
    cudaGetSymbolAddress((void**)&wqkvr,  g_wqkvr);
    cudaGetSymbolAddress((void**)&wgater, g_wgater);
    cudaGetSymbolAddress((void**)&woutr,  g_woutr);
    cudaGetSymbolAddress((void**)&rtab,   g_rope);

    // 0) pre-pass (3 launches -> QKV GEMM is launch #4 for ncu)
    pre_x_rope_kernel<<<(RN1 + RNR + 255) / 256, 256>>>(x, xr, rtab);
    pre_wqkv_kernel<<<(RN2 + 255) / 256, 256>>>(Wqkv, wqkvr);
    pre_wgo_kernel<<<(2 * RN3 + 255) / 256, 256>>>(Wgate, wgater, Wout, woutr);

    size_t gemm_smem = (size_t)GEMM_SMEM_FLOATS * sizeof(float);
    cudaFuncSetAttribute(mm_tf32_kernel,
                         cudaFuncAttributeMaxDynamicSharedMemorySize, (int)gemm_smem);

    // 1) QKV GEMM (launch #4 -> ncu target)
    mm_tf32_kernel<<<dim3(QKVN / BN, MROWS / BM), GTHR, gemm_smem>>>(
        xr, wqkvr, qkv, MROWS, QKVN, DMOD, 0, nullptr, nullptr);

    // 2) RMSNorm + RoPE + permute (launch #5)
    norm_rope_kernel<<<BATCH * NHEAD * TSEQ, 128>>>(qkv, rtab, q, k, v);

    // 3) Flash attention (launch #6)
    size_t fl_smem = (size_t)FSM_FLOATS * sizeof(float);
    cudaFuncSetAttribute(flash_mma_kernel,
                         cudaFuncAttributeMaxDynamicSharedMemorySize, (int)fl_smem);
    flash_mma_kernel<<<dim3(TSEQ / ABR, BATCH * NHEAD), 256, fl_smem>>>(q, k, v, o);

    // 4) gate GEMM with fused sigmoid * attn epilogue (launch #7)
    mm_tf32_kernel<<<dim3(DMOD / BN, MROWS / BM), GTHR, gemm_smem>>>(
        xr, wgater, g, MROWS, DMOD, DMOD, 1, bgate, o);

    // 5) output GEMM (launch #8)
    mm_tf32_kernel<<<dim3(DMOD / BN, MROWS / BM), GTHR, gemm_smem>>>(
        g, woutr, out, MROWS, DMOD, DMOD, 0, nullptr, nullptr);
}

// round 16
// speedup vs baseline: 1.1199x; 1.0025x over previous
#include <cuda_runtime.h>
#include <math.h>
#include <stdint.h>

// Problem constants (fixed by setup_inputs)
#define BATCH 2
#define TSEQ  2048
#define DMOD  2048
#define NHEAD 16
#define DHEAD 128
#define MROWS (BATCH * TSEQ)        // 4096
#define QKVN  (3 * DMOD)            // 6144

// ---------------------------------------------------------------------------
// Scratch (static device globals; no runtime allocation)
// ---------------------------------------------------------------------------
__device__ float g_qkv[(size_t)MROWS * QKVN];
__device__ float g_q[(size_t)BATCH * NHEAD * TSEQ * DHEAD];
__device__ float g_k[(size_t)BATCH * NHEAD * TSEQ * DHEAD];
__device__ float g_v[(size_t)BATCH * NHEAD * TSEQ * DHEAD];
__device__ float g_o[(size_t)MROWS * DMOD];     // attn out, [B,T,D] layout
__device__ float g_g[(size_t)MROWS * DMOD];
// tf32-rounded copies of inputs (plain row-major, same layout as source)
__device__ float g_xr[(size_t)MROWS * DMOD];
__device__ float g_wqkvr[(size_t)DMOD * QKVN];
__device__ float g_wgater[(size_t)DMOD * DMOD];
__device__ float g_woutr[(size_t)DMOD * DMOD];
// RoPE table: [t][j] -> (cos, sin), j = 0..63
__device__ float2 g_rope[(size_t)TSEQ * 64];

// ---------------------------------------------------------------------------
// Helpers
// ---------------------------------------------------------------------------
__device__ __forceinline__ uint32_t f2tf(float x) {
    uint32_t r;
    asm("cvt.rna.tf32.f32 %0, %1;" : "=r"(r) : "f"(x));
    return r;
}

__device__ __forceinline__ void mma_tf32(float* c, const uint32_t* a, const uint32_t* b) {
    asm volatile(
        "mma.sync.aligned.m16n8k8.row.col.f32.tf32.tf32.f32 "
        "{%0,%1,%2,%3},{%4,%5,%6,%7},{%8,%9},{%0,%1,%2,%3};\n"
        : "+f"(c[0]), "+f"(c[1]), "+f"(c[2]), "+f"(c[3])
        : "r"(a[0]), "r"(a[1]), "r"(a[2]), "r"(a[3]), "r"(b[0]), "r"(b[1]));
}

__device__ __forceinline__ void cpa16(void* dst, const void* src) {
    uint32_t d = (uint32_t)__cvta_generic_to_shared(dst);
    asm volatile("cp.async.cg.shared.global [%0], [%1], 16;" :: "r"(d), "l"(src));
}
#define CP_COMMIT() asm volatile("cp.async.commit_group;")
#define CP_WAIT0()  asm volatile("cp.async.wait_group 0;")
#define CP_WAIT1()  asm volatile("cp.async.wait_group 1;")
#define CP_WAIT2()  asm volatile("cp.async.wait_group 2;")

// ---------------------------------------------------------------------------
// Pre-pass kernels (3 launches so QKV GEMM lands at launch #4 for ncu).
// ---------------------------------------------------------------------------
#define RN1 ((MROWS * DMOD) / 4)    // x float4 count
#define RN2 ((DMOD * QKVN) / 4)     // W_qkv
#define RN3 ((DMOD * DMOD) / 4)     // W_gate / W_out
#define RNR (TSEQ * 64)             // rope entries

__device__ __forceinline__ void round_f4(const float4* src, float4* dst, int i) {
    float4 v = src[i];
    v.x = __uint_as_float(f2tf(v.x));
    v.y = __uint_as_float(f2tf(v.y));
    v.z = __uint_as_float(f2tf(v.z));
    v.w = __uint_as_float(f2tf(v.w));
    dst[i] = v;
}

__global__ void __launch_bounds__(256)
pre_x_rope_kernel(const float* __restrict__ x, float* __restrict__ xr,
                  float2* __restrict__ rtab)
{
    int i = blockIdx.x * blockDim.x + threadIdx.x;
    if (i < RN1) {
        round_f4((const float4*)x, (float4*)xr, i);
        return;
    }
    int idx = i - RN1;
    if (idx < RNR) {
        int t = idx >> 6;
        int j = idx & 63;
        double freq = exp(-((double)j / 64.0) * 9.210340371976184);  // ln(1e4)
        double ang = (double)t * freq;
        double sd, cd;
        sincos(ang, &sd, &cd);
        rtab[idx] = make_float2((float)cd, (float)sd);
    }
}

__global__ void __launch_bounds__(256)
pre_wqkv_kernel(const float* __restrict__ w, float* __restrict__ wr)
{
    int i = blockIdx.x * blockDim.x + threadIdx.x;
    if (i < RN2) round_f4((const float4*)w, (float4*)wr, i);
}

__global__ void __launch_bounds__(256)
pre_wgo_kernel(const float* __restrict__ wg, float* __restrict__ wgr,
               const float* __restrict__ wo, float* __restrict__ wor)
{
    int i = blockIdx.x * blockDim.x + threadIdx.x;
    if (i < RN3)            round_f4((const float4*)wg, (float4*)wgr, i);
    else if (i < 2 * RN3)   round_f4((const float4*)wo, (float4*)wor, i - RN3);
}

// ---------------------------------------------------------------------------
// tf32 GEMM: C[M,N] = A[M,K] @ B[K,N] (A,B pre-rounded, row-major).
// BM=BN=128, BK=32, 3-stage cp.async ring, 128 threads (4 warps),
// warp tile 64x64 (warps 2x2). 4 k-steps per stage, half the barriers
// of BK=16; ptxas overlaps next-step fragment LDS with current MMAs.
// mode 0: plain store; mode 1: C = round(sigmoid(acc+bias[n]) * gateO[m,n])
// ---------------------------------------------------------------------------
#define BM 128
#define BN 128
#define BK 32
#define BKP (BK + 4)    // 36 (bank-safe: 36g mod 32 = 4g, distinct for g 0..7)
#define BNP (BN + 8)    // 136
#define GST 3           // stages
#define GTHR 128        // threads

#define AS(s, r, c) Ash[(size_t)(s) * BM * BKP + (r) * BKP + (c)]
#define BS(s, r, c) Bsh[(size_t)(s) * BK * BNP + (r) * BNP + (c)]

#define GEMM_SMEM_FLOATS (GST * BM * BKP + GST * BK * BNP)   // 13824 + 13056

__global__ void __launch_bounds__(GTHR, 2)
mm_tf32_kernel(const float* __restrict__ A, const float* __restrict__ B,
               float* __restrict__ C, int M, int N, int K,
               int mode, const float* __restrict__ bias,
               const float* __restrict__ gateO)
{
    extern __shared__ float gsm[];
    float* Ash = gsm;
    float* Bsh = gsm + GST * BM * BKP;

    const int bx = blockIdx.x, by = blockIdx.y;
    const int tid = threadIdx.x;
    const int lane = tid & 31;
    const int warp = tid >> 5;          // 0..3
    const int wm = warp >> 1;           // 0..1 -> M offset wm*64
    const int wn = warp & 1;            // 0..1 -> N offset wn*64
    const int g  = lane >> 2;
    const int tg = lane & 3;

    const float* Abase = A + (size_t)(by * BM) * K;
    const float* Bbase = B + (size_t)(bx * BN);

    float acc[4][8][4];
#pragma unroll
    for (int im = 0; im < 4; im++)
#pragma unroll
        for (int in = 0; in < 8; in++)
#pragma unroll
            for (int j = 0; j < 4; j++) acc[im][in][j] = 0.f;

    const int KT = K / BK;

    // loaders (128 threads):
    // A: 128 rows x 32 floats = 1024 float4 -> 8 per thread
    // B: 32 rows x 128 floats = 1024 float4 -> 8 per thread
#pragma unroll
    for (int s = 0; s < 2; s++) {
        const int k0 = s * BK;
#pragma unroll
        for (int p = 0; p < 8; p++) {
            int idx = tid + p * GTHR;
            int r  = idx >> 3;
            int c4 = (idx & 7) << 2;
            cpa16(&AS(s, r, c4), Abase + (size_t)r * K + k0 + c4);
        }
#pragma unroll
        for (int p = 0; p < 8; p++) {
            int idx = tid + p * GTHR;
            int r  = idx >> 5;
            int c4 = (idx & 31) << 2;
            cpa16(&BS(s, r, c4), Bbase + (size_t)(k0 + r) * N + c4);
        }
        CP_COMMIT();
    }

    for (int kt = 0; kt < KT; kt++) {
        const int cur = kt % GST;
        if (kt + 1 < KT) { CP_WAIT1(); } else { CP_WAIT0(); }
        __syncthreads();

        if (kt + 2 < KT) {
            const int nxt = (kt + 2) % GST;
            const int k0 = (kt + 2) * BK;
#pragma unroll
            for (int p = 0; p < 8; p++) {
                int idx = tid + p * GTHR;
                int r  = idx >> 3;
                int c4 = (idx & 7) << 2;
                cpa16(&AS(nxt, r, c4), Abase + (size_t)r * K + k0 + c4);
            }
#pragma unroll
            for (int p = 0; p < 8; p++) {
                int idx = tid + p * GTHR;
                int r  = idx >> 5;
                int c4 = (idx & 31) << 2;
                cpa16(&BS(nxt, r, c4), Bbase + (size_t)(k0 + r) * N + c4);
            }
            CP_COMMIT();
        }

#pragma unroll
        for (int ik = 0; ik < 4; ik++) {
            uint32_t afr[4][4];
#pragma unroll
            for (int im = 0; im < 4; im++) {
                int r = wm * 64 + im * 16 + g;
                int c = ik * 8 + tg;
                afr[im][0] = __float_as_uint(AS(cur, r, c));
                afr[im][1] = __float_as_uint(AS(cur, r + 8, c));
                afr[im][2] = __float_as_uint(AS(cur, r, c + 4));
                afr[im][3] = __float_as_uint(AS(cur, r + 8, c + 4));
            }
            uint32_t bfr[8][2];
#pragma unroll
            for (int in = 0; in < 8; in++) {
                int cc = wn * 64 + in * 8 + g;
                int rk = ik * 8 + tg;
                bfr[in][0] = __float_as_uint(BS(cur, rk, cc));
                bfr[in][1] = __float_as_uint(BS(cur, rk + 4, cc));
            }
#pragma unroll
            for (int im = 0; im < 4; im++)
#pragma unroll
                for (int in = 0; in < 8; in++)
                    mma_tf32(acc[im][in], afr[im], bfr[in]);
        }
    }

    if (mode == 0) {
#pragma unroll
        for (int im = 0; im < 4; im++) {
            int r = by * BM + wm * 64 + im * 16 + g;
#pragma unroll
            for (int in = 0; in < 8; in++) {
                int c = bx * BN + wn * 64 + in * 8 + 2 * tg;
                *(float2*)(C + (size_t)r * N + c) =
                    make_float2(acc[im][in][0], acc[im][in][1]);
                *(float2*)(C + (size_t)(r + 8) * N + c) =
                    make_float2(acc[im][in][2], acc[im][in][3]);
            }
        }
    } else {
        // gateO in [B,T,D] -> index m*N + n, fully coalesced.
#pragma unroll
        for (int im = 0; im < 4; im++) {
            int r0 = by * BM + wm * 64 + im * 16 + g;
            int r1 = r0 + 8;
            float2 bv[8], go0[8], go1[8];
#pragma unroll
            for (int in = 0; in < 8; in++) {
                int c = bx * BN + wn * 64 + in * 8 + 2 * tg;
                bv[in]  = *(const float2*)(bias + c);
                go0[in] = *(const float2*)(gateO + (size_t)r0 * N + c);
                go1[in] = *(const float2*)(gateO + (size_t)r1 * N + c);
            }
#pragma unroll
            for (int in = 0; in < 8; in++) {
                int c = bx * BN + wn * 64 + in * 8 + 2 * tg;
                float s00 = 1.f / (1.f + __expf(-(acc[im][in][0] + bv[in].x)));
                float s01 = 1.f / (1.f + __expf(-(acc[im][in][1] + bv[in].y)));
                float s10 = 1.f / (1.f + __expf(-(acc[im][in][2] + bv[in].x)));
                float s11 = 1.f / (1.f + __expf(-(acc[im][in][3] + bv[in].y)));
                *(float2*)(C + (size_t)r0 * N + c) = make_float2(
                    __uint_as_float(f2tf(s00 * go0[in].x)),
                    __uint_as_float(f2tf(s01 * go0[in].y)));
                *(float2*)(C + (size_t)r1 * N + c) = make_float2(
                    __uint_as_float(f2tf(s10 * go1[in].x)),
                    __uint_as_float(f2tf(s11 * go1[in].y)));
            }
        }
    }
}

// ---------------------------------------------------------------------------
// RMSNorm + RoPE for q,k (plus v permute); outputs tf32-rounded.
// Q is pre-scaled by 1/sqrt(d). RoPE angles from precomputed table.
// ---------------------------------------------------------------------------
__global__ void __launch_bounds__(128)
norm_rope_kernel(const float* __restrict__ qkv,
                 const float2* __restrict__ rtab,
                 float* __restrict__ Qo, float* __restrict__ Ko,
                 float* __restrict__ Vo)
{
    const int rid = blockIdx.x;
    const int t  = rid & (TSEQ - 1);
    const int bh = rid >> 11;
    const int b  = bh >> 4;
    const int h  = bh & (NHEAD - 1);
    const int i  = threadIdx.x;

    const float* row = qkv + ((size_t)(b * TSEQ + t)) * QKVN + h * DHEAD;
    float qv = row[i];
    float kv = row[DMOD + i];
    float vv = row[2 * DMOD + i];

    float q2 = qv * qv, k2 = kv * kv;
#pragma unroll
    for (int o = 16; o; o >>= 1) {
        q2 += __shfl_xor_sync(0xffffffffu, q2, o);
        k2 += __shfl_xor_sync(0xffffffffu, k2, o);
    }
    __shared__ float rq[4], rk[4];
    if ((i & 31) == 0) { rq[i >> 5] = q2; rk[i >> 5] = k2; }
    __syncthreads();
    float ssq = rq[0] + rq[1] + rq[2] + rq[3];
    float ssk = rk[0] + rk[1] + rk[2] + rk[3];
    float rnq = rsqrtf(ssq * (1.f / DHEAD) + 1e-6f);
    float rnk = rsqrtf(ssk * (1.f / DHEAD) + 1e-6f);

    __shared__ float sq[DHEAD], sk[DHEAD];
    sq[i] = qv * rnq;
    sk[i] = kv * rnk;
    __syncthreads();

    const int j = i & 63;
    float2 cs = rtab[(size_t)t * 64 + j];
    float c = cs.x, s = cs.y;

    float oq, ok;
    if (i < 64) {
        oq = sq[i] * c - sq[i + 64] * s;
        ok = sk[i] * c - sk[i + 64] * s;
    } else {
        oq = sq[i - 64] * s + sq[i] * c;
        ok = sk[i - 64] * s + sk[i] * c;
    }
    const float qscale = 0.08838834764831845f;  // 1/sqrt(128), folded into Q
    size_t oidx = ((size_t)bh * TSEQ + t) * DHEAD + i;
    Qo[oidx] = __uint_as_float(f2tf(oq * qscale));
    Ko[oidx] = __uint_as_float(f2tf(ok));
    Vo[oidx] = __uint_as_float(f2tf(vv));
}

// ---------------------------------------------------------------------------
// Flash attention (causal), tf32 mma. Br=128, Bc=64, 256 threads (8 warps).
// K and V triple-buffered with a 2-tile prefetch window. Q staging overlays
// K buffers 0-1; P converted reg->reg via shfl. Scale pre-folded into Q.
// O is written in [B,T,D] layout (permute fused -> coalesced gate epilogue).
// ---------------------------------------------------------------------------
#define ABR 128
#define ABC 64
#define DP  132            // d + 4
#define KTF (ABR / ABC)    // 2 kv-tiles per q-tile
#define NBUF 3
#define TILEF (ABC * DP)   // 8448 floats per tile buffer
#define FSM_FLOATS (2 * NBUF * TILEF)   // 50688 floats = 202752 B

__global__ void __launch_bounds__(256, 1)
flash_mma_kernel(const float* __restrict__ Qg, const float* __restrict__ Kg,
                 const float* __restrict__ Vg, float* __restrict__ Og)
{
    extern __shared__ float fsm[];

    const int qt = (gridDim.x - 1) - blockIdx.x;   // heavy tiles first
    const int bh = blockIdx.y;
    const int tid  = threadIdx.x;
    const int lane = tid & 31;
    const int w    = tid >> 5;          // warp 0..7
    const int g    = lane >> 2;
    const int tg   = lane & 3;

    const float* Qb = Qg + (size_t)bh * TSEQ * DHEAD;
    const float* Kb = Kg + (size_t)bh * TSEQ * DHEAD;
    const float* Vb = Vg + (size_t)bh * TSEQ * DHEAD;

    const int ktmax = KTF * (qt + 1);

    // --- prologue: stage Q (128x128) into K buffers 0-1 region
#pragma unroll
    for (int p = 0; p < 16; p++) {
        int idx = tid + p * 256;
        int r = idx >> 5;
        int c = (idx & 31) << 2;
        cpa16(&fsm[r * DP + c], Qb + (size_t)(qt * ABR + r) * DHEAD + c);
    }
    CP_COMMIT();
    CP_WAIT0();
    __syncthreads();

    uint32_t qf[16][4];
    {
        int r = w * 16 + g;
#pragma unroll
        for (int ik = 0; ik < 16; ik++) {
            int c = ik * 8 + tg;
            qf[ik][0] = __float_as_uint(fsm[r * DP + c]);
            qf[ik][1] = __float_as_uint(fsm[(r + 8) * DP + c]);
            qf[ik][2] = __float_as_uint(fsm[r * DP + c + 4]);
            qf[ik][3] = __float_as_uint(fsm[(r + 8) * DP + c + 4]);
        }
    }
    __syncthreads();   // all warps done with Q before K(0)/K(1) overwrite it

    // prefetch tiles 0 and 1 (one group each: {K,V})
#pragma unroll
    for (int s = 0; s < 2; s++) {
        if (s < ktmax) {
            float* ks = fsm + s * TILEF;
            float* vs = fsm + (NBUF + s) * TILEF;
            const float* kp = Kb + (size_t)s * ABC * DHEAD;
            const float* vp = Vb + (size_t)s * ABC * DHEAD;
#pragma unroll
            for (int p = 0; p < 8; p++) {
                int idx = tid + p * 256;
                int r = idx >> 5;
                int c = (idx & 31) << 2;
                cpa16(&ks[r * DP + c], kp + (size_t)r * DHEAD + c);
                cpa16(&vs[r * DP + c], vp + (size_t)r * DHEAD + c);
            }
            CP_COMMIT();
        }
    }

    float oacc[16][4];
#pragma unroll
    for (int in = 0; in < 16; in++)
#pragma unroll
        for (int j = 0; j < 4; j++) oacc[in][j] = 0.f;
    float m_i[2] = {-INFINITY, -INFINITY};
    float l_i[2] = {0.f, 0.f};

    const int rlo = qt * ABR + w * 16 + g;

    for (int kt = 0; kt < ktmax; kt++) {
        if (kt + 2 < ktmax) {
            int s = (kt + 2) % NBUF;
            float* ks = fsm + s * TILEF;
            float* vs = fsm + (NBUF + s) * TILEF;
            const float* kp = Kb + (size_t)(kt + 2) * ABC * DHEAD;
            const float* vp = Vb + (size_t)(kt + 2) * ABC * DHEAD;
#pragma unroll
            for (int p = 0; p < 8; p++) {
                int idx = tid + p * 256;
                int r = idx >> 5;
                int c = (idx & 31) << 2;
                cpa16(&ks[r * DP + c], kp + (size_t)r * DHEAD + c);
                cpa16(&vs[r * DP + c], vp + (size_t)r * DHEAD + c);
            }
            CP_COMMIT();
            CP_WAIT2();
        } else if (kt + 1 < ktmax) {
            CP_WAIT1();
        } else {
            CP_WAIT0();
        }
        __syncthreads();

        const float* Ksc = fsm + (kt % NBUF) * TILEF;
        const float* Vsc = fsm + (NBUF + kt % NBUF) * TILEF;

        // S = Q @ K^T  (warp: 16 x 64; 8 n-atoms)
        float sacc[8][4];
#pragma unroll
        for (int in = 0; in < 8; in++)
#pragma unroll
            for (int j = 0; j < 4; j++) sacc[in][j] = 0.f;

#pragma unroll
        for (int ik = 0; ik < 16; ik++) {
#pragma unroll
            for (int in = 0; in < 8; in++) {
                uint32_t bf[2];
                int srow = in * 8 + g;
                int dcol = ik * 8 + tg;
                bf[0] = __float_as_uint(Ksc[srow * DP + dcol]);
                bf[1] = __float_as_uint(Ksc[srow * DP + dcol + 4]);
                mma_tf32(sacc[in], qf[ik], bf);
            }
        }

        // causal mask (band tiles only)
        if (kt >= KTF * qt) {
#pragma unroll
            for (int in = 0; in < 8; in++) {
                int cbase = kt * ABC + in * 8 + 2 * tg;
#pragma unroll
                for (int j = 0; j < 4; j++) {
                    int cg = cbase + (j & 1);
                    int rg = rlo + (j >> 1) * 8;
                    if (cg > rg) sacc[in][j] = -INFINITY;
                }
            }
        }

        // online softmax per owned row (rr=0: row g ; rr=1: row g+8)
        float alpha[2];
#pragma unroll
        for (int rr = 0; rr < 2; rr++) {
            float pm = -INFINITY;
#pragma unroll
            for (int in = 0; in < 8; in++) {
                pm = fmaxf(pm, sacc[in][2 * rr]);
                pm = fmaxf(pm, sacc[in][2 * rr + 1]);
            }
            pm = fmaxf(pm, __shfl_xor_sync(0xffffffffu, pm, 1));
            pm = fmaxf(pm, __shfl_xor_sync(0xffffffffu, pm, 2));
            float mnew = fmaxf(m_i[rr], pm);
            float ps = 0.f;
#pragma unroll
            for (int in = 0; in < 8; in++) {
                float e0 = __expf(sacc[in][2 * rr]     - mnew);
                float e1 = __expf(sacc[in][2 * rr + 1] - mnew);
                sacc[in][2 * rr] = e0;
                sacc[in][2 * rr + 1] = e1;
                ps += e0 + e1;
            }
            ps += __shfl_xor_sync(0xffffffffu, ps, 1);
            ps += __shfl_xor_sync(0xffffffffu, ps, 2);
            alpha[rr] = __expf(m_i[rr] - mnew);
            l_i[rr] = l_i[rr] * alpha[rr] + ps;
            m_i[rr] = mnew;
        }
#pragma unroll
        for (int in = 0; in < 16; in++) {
            oacc[in][0] *= alpha[0]; oacc[in][1] *= alpha[0];
            oacc[in][2] *= alpha[1]; oacc[in][3] *= alpha[1];
        }

        // O += P @ V  (P converted C-frag -> A-frag via shfl; raw fp32 bits)
#pragma unroll
        for (int ik = 0; ik < 8; ik++) {
            const int srcA = (lane & 28) | (tg >> 1);
            const int srcB = srcA + 2;
            const bool odd = (tg & 1) != 0;
            float e0 = __shfl_sync(0xffffffffu, sacc[ik][0], srcA);
            float e1 = __shfl_sync(0xffffffffu, sacc[ik][1], srcA);
            float e2 = __shfl_sync(0xffffffffu, sacc[ik][2], srcA);
            float e3 = __shfl_sync(0xffffffffu, sacc[ik][3], srcA);
            float f0 = __shfl_sync(0xffffffffu, sacc[ik][0], srcB);
            float f1 = __shfl_sync(0xffffffffu, sacc[ik][1], srcB);
            float f2 = __shfl_sync(0xffffffffu, sacc[ik][2], srcB);
            float f3 = __shfl_sync(0xffffffffu, sacc[ik][3], srcB);
            uint32_t af[4];
            af[0] = __float_as_uint(odd ? e1 : e0);   // P[g][tg]
            af[1] = __float_as_uint(odd ? e3 : e2);   // P[g+8][tg]
            af[2] = __float_as_uint(odd ? f1 : f0);   // P[g][tg+4]
            af[3] = __float_as_uint(odd ? f3 : f2);   // P[g+8][tg+4]
#pragma unroll
            for (int in = 0; in < 16; in++) {
                uint32_t bf[2];
                int krow = ik * 8 + tg;
                int dcol = in * 8 + g;
                bf[0] = __float_as_uint(Vsc[krow * DP + dcol]);
                bf[1] = __float_as_uint(Vsc[(krow + 4) * DP + dcol]);
                mma_tf32(oacc[in], af, bf);
            }
        }
        __syncthreads();   // all warps done with buffer kt%3 before refill
    }

    // epilogue: write O in [B,T,D] layout (fused permute)
    float inv0 = 1.f / l_i[0];
    float inv1 = 1.f / l_i[1];
    {
        const int b = bh >> 4;
        const int h = bh & (NHEAD - 1);
        const int t0 = qt * ABR + w * 16 + g;
        float* O0 = Og + ((size_t)(b * TSEQ + t0)     ) * DMOD + h * DHEAD;
        float* O1 = Og + ((size_t)(b * TSEQ + t0 + 8) ) * DMOD + h * DHEAD;
#pragma unroll
        for (int in = 0; in < 16; in++) {
            int c = in * 8 + 2 * tg;
            *(float2*)(O0 + c) =
                make_float2(oacc[in][0] * inv0, oacc[in][1] * inv0);
            *(float2*)(O1 + c) =
                make_float2(oacc[in][2] * inv1, oacc[in][3] * inv1);
        }
    }
}

// ---------------------------------------------------------------------------
// Host launcher
// ---------------------------------------------------------------------------
extern "C" void kernel_launch(void* const* d_in, const int* in_sizes, int n_in,
                              void* d_out, int out_size)
{
    const float* x     = (const float*)d_in[0];
    const float* Wqkv  = (const float*)d_in[1];
    const float* Wout  = (const float*)d_in[2];
    const float* Wgate = (const float*)d_in[3];
    const float* bgate = (const float*)d_in[4];
    float* out = (float*)d_out;

    float *qkv, *q, *k, *v, *o, *g, *xr, *wqkvr, *wgater, *woutr;
    float2* rtab;
    cudaGetSymbolAddress((void**)&qkv,    g_qkv);
    cudaGetSymbolAddress((void**)&q,      g_q);
    cudaGetSymbolAddress((void**)&k,      g_k);
    cudaGetSymbolAddress((void**)&v,      g_v);
    cudaGetSymbolAddress((void**)&o,      g_o);
    cudaGetSymbolAddress((void**)&g,      g_g);
    cudaGetSymbolAddress((void**)&xr,     g_xr);
    cudaGetSymbolAddress((void**)&wqkvr,  g_wqkvr);
    cudaGetSymbolAddress((void**)&wgater, g_wgater);
    cudaGetSymbolAddress((void**)&woutr,  g_woutr);
    cudaGetSymbolAddress((void**)&rtab,   g_rope);

    // 0) pre-pass (3 launches -> QKV GEMM is launch #4 for ncu)
    pre_x_rope_kernel<<<(RN1 + RNR + 255) / 256, 256>>>(x, xr, rtab);
    pre_wqkv_kernel<<<(RN2 + 255) / 256, 256>>>(Wqkv, wqkvr);
    pre_wgo_kernel<<<(2 * RN3 + 255) / 256, 256>>>(Wgate, wgater, Wout, woutr);

    size_t gemm_smem = (size_t)GEMM_SMEM_FLOATS * sizeof(float);
    cudaFuncSetAttribute(mm_tf32_kernel,
                         cudaFuncAttributeMaxDynamicSharedMemorySize, (int)gemm_smem);

    // 1) QKV GEMM (launch #4 -> ncu target)
    mm_tf32_kernel<<<dim3(QKVN / BN, MROWS / BM), GTHR, gemm_smem>>>(
        xr, wqkvr, qkv, MROWS, QKVN, DMOD, 0, nullptr, nullptr);

    // 2) RMSNorm + RoPE + permute (launch #5)
    norm_rope_kernel<<<BATCH * NHEAD * TSEQ, 128>>>(qkv, rtab, q, k, v);

    // 3) Flash attention (launch #6)
    size_t fl_smem = (size_t)FSM_FLOATS * sizeof(float);
    cudaFuncSetAttribute(flash_mma_kernel,
                         cudaFuncAttributeMaxDynamicSharedMemorySize, (int)fl_smem);
    flash_mma_kernel<<<dim3(TSEQ / ABR, BATCH * NHEAD), 256, fl_smem>>>(q, k, v, o);

    // 4) gate GEMM with fused sigmoid * attn epilogue (launch #7)
    mm_tf32_kernel<<<dim3(DMOD / BN, MROWS / BM), GTHR, gemm_smem>>>(
        xr, wgater, g, MROWS, DMOD, DMOD, 1, bgate, o);

    // 5) output GEMM (launch #8)
    mm_tf32_kernel<<<dim3(DMOD / BN, MROWS / BM), GTHR, gemm_smem>>>(
        g, woutr, out, MROWS, DMOD, DMOD, 0, nullptr, nullptr);
}

// round 17
// speedup vs baseline: 1.2011x; 1.0725x over previous
#include <cuda_runtime.h>
#include <math.h>
#include <stdint.h>

// Problem constants (fixed by setup_inputs)
#define BATCH 2
#define TSEQ  2048
#define DMOD  2048
#define NHEAD 16
#define DHEAD 128
#define MROWS (BATCH * TSEQ)        // 4096
#define QKVN  (3 * DMOD)            // 6144

// ---------------------------------------------------------------------------
// Scratch (static device globals; no runtime allocation)
// ---------------------------------------------------------------------------
__device__ float g_qkv[(size_t)MROWS * QKVN];
__device__ float g_q[(size_t)BATCH * NHEAD * TSEQ * DHEAD];   // d-interleaved
__device__ float g_k[(size_t)BATCH * NHEAD * TSEQ * DHEAD];   // d-interleaved
__device__ float g_v[(size_t)BATCH * NHEAD * TSEQ * DHEAD];   // true layout
__device__ float g_o[(size_t)MROWS * DMOD];     // attn out, [B,T,D] true layout
__device__ float g_g[(size_t)MROWS * DMOD];     // gated, K-PERMUTED (A of out-GEMM)
// tf32-rounded copies (xr is k-permuted within 8-groups; W's are plain)
__device__ float g_xr[(size_t)MROWS * DMOD];
__device__ float g_wqkvr[(size_t)DMOD * QKVN];
__device__ float g_wgater[(size_t)DMOD * DMOD];
__device__ float g_woutr[(size_t)DMOD * DMOD];
// RoPE table: [t][j] -> (cos, sin), j = 0..63
__device__ float2 g_rope[(size_t)TSEQ * 64];

// ---------------------------------------------------------------------------
// Helpers
// ---------------------------------------------------------------------------
__device__ __forceinline__ uint32_t f2tf(float x) {
    uint32_t r;
    asm("cvt.rna.tf32.f32 %0, %1;" : "=r"(r) : "f"(x));
    return r;
}

// permutation within 8-group: pos(k) = k<4 ? 2k : 2(k-4)+1
__device__ __forceinline__ int kpos(int k) { return (k < 4) ? 2 * k : 2 * (k - 4) + 1; }

__device__ __forceinline__ void mma_tf32(float* c, const uint32_t* a, const uint32_t* b) {
    asm volatile(
        "mma.sync.aligned.m16n8k8.row.col.f32.tf32.tf32.f32 "
        "{%0,%1,%2,%3},{%4,%5,%6,%7},{%8,%9},{%0,%1,%2,%3};\n"
        : "+f"(c[0]), "+f"(c[1]), "+f"(c[2]), "+f"(c[3])
        : "r"(a[0]), "r"(a[1]), "r"(a[2]), "r"(a[3]), "r"(b[0]), "r"(b[1]));
}

__device__ __forceinline__ void cpa16(void* dst, const void* src) {
    uint32_t d = (uint32_t)__cvta_generic_to_shared(dst);
    asm volatile("cp.async.cg.shared.global [%0], [%1], 16;" :: "r"(d), "l"(src));
}
#define CP_COMMIT() asm volatile("cp.async.commit_group;")
#define CP_WAIT0()  asm volatile("cp.async.wait_group 0;")
#define CP_WAIT1()  asm volatile("cp.async.wait_group 1;")
#define CP_WAIT2()  asm volatile("cp.async.wait_group 2;")

// ---------------------------------------------------------------------------
// Pre-pass kernels (3 launches so QKV GEMM lands at launch #4 for ncu).
// ---------------------------------------------------------------------------
#define RNX (MROWS * DMOD / 8)      // x 8-float groups
#define RN2 ((DMOD * QKVN) / 4)     // W_qkv float4
#define RN3 ((DMOD * DMOD) / 4)     // W_gate / W_out float4
#define RNR (TSEQ * 64)             // rope entries

__device__ __forceinline__ void round_f4(const float4* src, float4* dst, int i) {
    float4 v = src[i];
    v.x = __uint_as_float(f2tf(v.x));
    v.y = __uint_as_float(f2tf(v.y));
    v.z = __uint_as_float(f2tf(v.z));
    v.w = __uint_as_float(f2tf(v.w));
    dst[i] = v;
}

// launch #1: round + k-interleave x (thread owns one 8-float group), + rope
__global__ void __launch_bounds__(256)
pre_x_rope_kernel(const float* __restrict__ x, float* __restrict__ xr,
                  float2* __restrict__ rtab)
{
    int i = blockIdx.x * blockDim.x + threadIdx.x;
    if (i < RNX) {
        const float* s = x + (size_t)i * 8;
        float o[8];
#pragma unroll
        for (int k = 0; k < 8; k++)
            o[kpos(k)] = __uint_as_float(f2tf(s[k]));
        float4* d = (float4*)(xr + (size_t)i * 8);
        d[0] = make_float4(o[0], o[1], o[2], o[3]);
        d[1] = make_float4(o[4], o[5], o[6], o[7]);
        return;
    }
    int idx = i - RNX;
    if (idx < RNR) {
        int t = idx >> 6;
        int j = idx & 63;
        double freq = exp(-((double)j / 64.0) * 9.210340371976184);  // ln(1e4)
        double ang = (double)t * freq;
        double sd, cd;
        sincos(ang, &sd, &cd);
        rtab[idx] = make_float2((float)cd, (float)sd);
    }
}

__global__ void __launch_bounds__(256)
pre_wqkv_kernel(const float* __restrict__ w, float* __restrict__ wr)
{
    int i = blockIdx.x * blockDim.x + threadIdx.x;
    if (i < RN2) round_f4((const float4*)w, (float4*)wr, i);
}

__global__ void __launch_bounds__(256)
pre_wgo_kernel(const float* __restrict__ wg, float* __restrict__ wgr,
               const float* __restrict__ wo, float* __restrict__ wor)
{
    int i = blockIdx.x * blockDim.x + threadIdx.x;
    if (i < RN3)            round_f4((const float4*)wg, (float4*)wgr, i);
    else if (i < 2 * RN3)   round_f4((const float4*)wo, (float4*)wor, i - RN3);
}

// ---------------------------------------------------------------------------
// tf32 GEMM: C[M,N] = A[M,K] @ B[K,N].
// A is k-interleaved within 8-groups -> A-fragment pairs load as float2
// (8 LDS.64 instead of 16 LDS.32 per warp-kstep). B path unchanged.
// BM=BN=128, BK=32, 3-stage cp.async, 128 threads, warp tile 64x64.
// mode 0: plain store (true layout); mode 1: gate epilogue, C K-PERMUTED.
// ---------------------------------------------------------------------------
#define BM 128
#define BN 128
#define BK 32
#define BKP 40          // A row stride (160B; float2 frags phase-conflict-free)
#define BNP (BN + 8)    // 136
#define GST 3           // stages
#define GTHR 128        // threads

#define AS(s, r, c) Ash[(size_t)(s) * BM * BKP + (r) * BKP + (c)]
#define BS(s, r, c) Bsh[(size_t)(s) * BK * BNP + (r) * BNP + (c)]

#define GEMM_SMEM_FLOATS (GST * BM * BKP + GST * BK * BNP)   // 15360 + 13056

__global__ void __launch_bounds__(GTHR, 2)
mm_tf32_kernel(const float* __restrict__ A, const float* __restrict__ B,
               float* __restrict__ C, int M, int N, int K,
               int mode, const float* __restrict__ bias,
               const float* __restrict__ gateO)
{
    extern __shared__ float gsm[];
    float* Ash = gsm;
    float* Bsh = gsm + GST * BM * BKP;

    const int bx = blockIdx.x, by = blockIdx.y;
    const int tid = threadIdx.x;
    const int lane = tid & 31;
    const int warp = tid >> 5;          // 0..3
    const int wm = warp >> 1;           // 0..1 -> M offset wm*64
    const int wn = warp & 1;            // 0..1 -> N offset wn*64
    const int g  = lane >> 2;
    const int tg = lane & 3;

    const float* Abase = A + (size_t)(by * BM) * K;
    const float* Bbase = B + (size_t)(bx * BN);

    float acc[4][8][4];
#pragma unroll
    for (int im = 0; im < 4; im++)
#pragma unroll
        for (int in = 0; in < 8; in++)
#pragma unroll
            for (int j = 0; j < 4; j++) acc[im][in][j] = 0.f;

    const int KT = K / BK;

    // loaders (128 threads):
    // A: 128 rows x 32 floats = 1024 float4 -> 8 per thread (copy verbatim;
    //    global A is already k-interleaved)
    // B: 32 rows x 128 floats = 1024 float4 -> 8 per thread
#pragma unroll
    for (int s = 0; s < 2; s++) {
        const int k0 = s * BK;
#pragma unroll
        for (int p = 0; p < 8; p++) {
            int idx = tid + p * GTHR;
            int r  = idx >> 3;
            int c4 = (idx & 7) << 2;
            cpa16(&AS(s, r, c4), Abase + (size_t)r * K + k0 + c4);
        }
#pragma unroll
        for (int p = 0; p < 8; p++) {
            int idx = tid + p * GTHR;
            int r  = idx >> 5;
            int c4 = (idx & 31) << 2;
            cpa16(&BS(s, r, c4), Bbase + (size_t)(k0 + r) * N + c4);
        }
        CP_COMMIT();
    }

    for (int kt = 0; kt < KT; kt++) {
        const int cur = kt % GST;
        if (kt + 1 < KT) { CP_WAIT1(); } else { CP_WAIT0(); }
        __syncthreads();

        if (kt + 2 < KT) {
            const int nxt = (kt + 2) % GST;
            const int k0 = (kt + 2) * BK;
#pragma unroll
            for (int p = 0; p < 8; p++) {
                int idx = tid + p * GTHR;
                int r  = idx >> 3;
                int c4 = (idx & 7) << 2;
                cpa16(&AS(nxt, r, c4), Abase + (size_t)r * K + k0 + c4);
            }
#pragma unroll
            for (int p = 0; p < 8; p++) {
                int idx = tid + p * GTHR;
                int r  = idx >> 5;
                int c4 = (idx & 31) << 2;
                cpa16(&BS(nxt, r, c4), Bbase + (size_t)(k0 + r) * N + c4);
            }
            CP_COMMIT();
        }

#pragma unroll
        for (int ik = 0; ik < 4; ik++) {
            uint32_t afr[4][4];
#pragma unroll
            for (int im = 0; im < 4; im++) {
                int r = wm * 64 + im * 16 + g;
                int c = ik * 8 + 2 * tg;    // interleaved: (k=tg, k=tg+4) adjacent
                float2 lo = *(const float2*)&AS(cur, r, c);
                float2 hi = *(const float2*)&AS(cur, r + 8, c);
                afr[im][0] = __float_as_uint(lo.x);
                afr[im][2] = __float_as_uint(lo.y);
                afr[im][1] = __float_as_uint(hi.x);
                afr[im][3] = __float_as_uint(hi.y);
            }
            uint32_t bfr[8][2];
#pragma unroll
            for (int in = 0; in < 8; in++) {
                int cc = wn * 64 + in * 8 + g;
                int rk = ik * 8 + tg;
                bfr[in][0] = __float_as_uint(BS(cur, rk, cc));
                bfr[in][1] = __float_as_uint(BS(cur, rk + 4, cc));
            }
#pragma unroll
            for (int im = 0; im < 4; im++)
#pragma unroll
                for (int in = 0; in < 8; in++)
                    mma_tf32(acc[im][in], afr[im], bfr[in]);
        }
    }

    if (mode == 0) {
#pragma unroll
        for (int im = 0; im < 4; im++) {
            int r = by * BM + wm * 64 + im * 16 + g;
#pragma unroll
            for (int in = 0; in < 8; in++) {
                int c = bx * BN + wn * 64 + in * 8 + 2 * tg;
                *(float2*)(C + (size_t)r * N + c) =
                    make_float2(acc[im][in][0], acc[im][in][1]);
                *(float2*)(C + (size_t)(r + 8) * N + c) =
                    make_float2(acc[im][in][2], acc[im][in][3]);
            }
        }
    } else {
        // gate epilogue. C = g feeds the out-GEMM as A -> write K-PERMUTED:
        // true cols (base+2tg, base+2tg+1) -> atom positions (p0, p0+2).
        const int p0 = (tg < 2) ? 4 * tg : 4 * tg - 7;
#pragma unroll
        for (int im = 0; im < 4; im++) {
            int r0 = by * BM + wm * 64 + im * 16 + g;
            int r1 = r0 + 8;
            float2 bv[8], go0[8], go1[8];
#pragma unroll
            for (int in = 0; in < 8; in++) {
                int c = bx * BN + wn * 64 + in * 8 + 2 * tg;
                bv[in]  = *(const float2*)(bias + c);
                go0[in] = *(const float2*)(gateO + (size_t)r0 * N + c);
                go1[in] = *(const float2*)(gateO + (size_t)r1 * N + c);
            }
#pragma unroll
            for (int in = 0; in < 8; in++) {
                int nb = bx * BN + wn * 64 + in * 8;   // atom-aligned base
                float s00 = 1.f / (1.f + __expf(-(acc[im][in][0] + bv[in].x)));
                float s01 = 1.f / (1.f + __expf(-(acc[im][in][1] + bv[in].y)));
                float s10 = 1.f / (1.f + __expf(-(acc[im][in][2] + bv[in].x)));
                float s11 = 1.f / (1.f + __expf(-(acc[im][in][3] + bv[in].y)));
                C[(size_t)r0 * N + nb + p0]     = __uint_as_float(f2tf(s00 * go0[in].x));
                C[(size_t)r0 * N + nb + p0 + 2] = __uint_as_float(f2tf(s01 * go0[in].y));
                C[(size_t)r1 * N + nb + p0]     = __uint_as_float(f2tf(s10 * go1[in].x));
                C[(size_t)r1 * N + nb + p0 + 2] = __uint_as_float(f2tf(s11 * go1[in].y));
            }
        }
    }
}

// ---------------------------------------------------------------------------
// RMSNorm + RoPE for q,k (plus v permute); outputs tf32-rounded.
// Q,K written D-INTERLEAVED within 8-groups (flash loads frag pairs as
// float2). V stays true layout. Q pre-scaled by 1/sqrt(d).
// ---------------------------------------------------------------------------
__global__ void __launch_bounds__(128)
norm_rope_kernel(const float* __restrict__ qkv,
                 const float2* __restrict__ rtab,
                 float* __restrict__ Qo, float* __restrict__ Ko,
                 float* __restrict__ Vo)
{
    const int rid = blockIdx.x;
    const int t  = rid & (TSEQ - 1);
    const int bh = rid >> 11;
    const int b  = bh >> 4;
    const int h  = bh & (NHEAD - 1);
    const int i  = threadIdx.x;

    const float* row = qkv + ((size_t)(b * TSEQ + t)) * QKVN + h * DHEAD;
    float qv = row[i];
    float kv = row[DMOD + i];
    float vv = row[2 * DMOD + i];

    float q2 = qv * qv, k2 = kv * kv;
#pragma unroll
    for (int o = 16; o; o >>= 1) {
        q2 += __shfl_xor_sync(0xffffffffu, q2, o);
        k2 += __shfl_xor_sync(0xffffffffu, k2, o);
    }
    __shared__ float rq[4], rk[4];
    if ((i & 31) == 0) { rq[i >> 5] = q2; rk[i >> 5] = k2; }
    __syncthreads();
    float ssq = rq[0] + rq[1] + rq[2] + rq[3];
    float ssk = rk[0] + rk[1] + rk[2] + rk[3];
    float rnq = rsqrtf(ssq * (1.f / DHEAD) + 1e-6f);
    float rnk = rsqrtf(ssk * (1.f / DHEAD) + 1e-6f);

    __shared__ float sq[DHEAD], sk[DHEAD];
    sq[i] = qv * rnq;
    sk[i] = kv * rnk;
    __syncthreads();

    const int j = i & 63;
    float2 cs = rtab[(size_t)t * 64 + j];
    float c = cs.x, s = cs.y;

    float oq, ok;
    if (i < 64) {
        oq = sq[i] * c - sq[i + 64] * s;
        ok = sk[i] * c - sk[i + 64] * s;
    } else {
        oq = sq[i - 64] * s + sq[i] * c;
        ok = sk[i - 64] * s + sk[i] * c;
    }
    const float qscale = 0.08838834764831845f;  // 1/sqrt(128), folded into Q
    const int ip = (i & ~7) | kpos(i & 7);      // d-interleaved position
    size_t base = ((size_t)bh * TSEQ + t) * DHEAD;
    Qo[base + ip] = __uint_as_float(f2tf(oq * qscale));
    Ko[base + ip] = __uint_as_float(f2tf(ok));
    Vo[base + i]  = __uint_as_float(f2tf(vv));
}

// ---------------------------------------------------------------------------
// Flash attention (causal), tf32 mma. Br=128, Bc=64, 256 threads (8 warps).
// Q,K are d-interleaved -> S-loop K fragments load as single LDS.64
// (128 instead of 256 LDS per warp-tile). DP=136 keeps float2 loads
// phase-conflict-free. K,V triple-buffered (2-tile prefetch window);
// Q staging overlays K buffers 0-1; P via shfl. O written [B,T,D].
// ---------------------------------------------------------------------------
#define ABR 128
#define ABC 64
#define DP  136            // d + 8 (float2 phase-conflict-free)
#define KTF (ABR / ABC)    // 2 kv-tiles per q-tile
#define NBUF 3
#define TILEF (ABC * DP)   // 8704 floats per tile buffer
#define FSM_FLOATS (2 * NBUF * TILEF)   // 52224 floats = 208896 B

__global__ void __launch_bounds__(256, 1)
flash_mma_kernel(const float* __restrict__ Qg, const float* __restrict__ Kg,
                 const float* __restrict__ Vg, float* __restrict__ Og)
{
    extern __shared__ float fsm[];

    const int qt = (gridDim.x - 1) - blockIdx.x;   // heavy tiles first
    const int bh = blockIdx.y;
    const int tid  = threadIdx.x;
    const int lane = tid & 31;
    const int w    = tid >> 5;          // warp 0..7
    const int g    = lane >> 2;
    const int tg   = lane & 3;

    const float* Qb = Qg + (size_t)bh * TSEQ * DHEAD;
    const float* Kb = Kg + (size_t)bh * TSEQ * DHEAD;
    const float* Vb = Vg + (size_t)bh * TSEQ * DHEAD;

    const int ktmax = KTF * (qt + 1);

    // --- prologue: stage Q (128x128, d-interleaved) into K buffers 0-1
#pragma unroll
    for (int p = 0; p < 16; p++) {
        int idx = tid + p * 256;
        int r = idx >> 5;
        int c = (idx & 31) << 2;
        cpa16(&fsm[r * DP + c], Qb + (size_t)(qt * ABR + r) * DHEAD + c);
    }
    CP_COMMIT();
    CP_WAIT0();
    __syncthreads();

    uint32_t qf[16][4];
    {
        int r = w * 16 + g;
#pragma unroll
        for (int ik = 0; ik < 16; ik++) {
            int c = ik * 8 + 2 * tg;    // interleaved: (d=tg, d=tg+4) adjacent
            float2 lo = *(const float2*)&fsm[r * DP + c];
            float2 hi = *(const float2*)&fsm[(r + 8) * DP + c];
            qf[ik][0] = __float_as_uint(lo.x);
            qf[ik][2] = __float_as_uint(lo.y);
            qf[ik][1] = __float_as_uint(hi.x);
            qf[ik][3] = __float_as_uint(hi.y);
        }
    }
    __syncthreads();   // all warps done with Q before K(0)/K(1) overwrite it

    // prefetch tiles 0 and 1 (one group each: {K,V})
#pragma unroll
    for (int s = 0; s < 2; s++) {
        if (s < ktmax) {
            float* ks = fsm + s * TILEF;
            float* vs = fsm + (NBUF + s) * TILEF;
            const float* kp = Kb + (size_t)s * ABC * DHEAD;
            const float* vp = Vb + (size_t)s * ABC * DHEAD;
#pragma unroll
            for (int p = 0; p < 8; p++) {
                int idx = tid + p * 256;
                int r = idx >> 5;
                int c = (idx & 31) << 2;
                cpa16(&ks[r * DP + c], kp + (size_t)r * DHEAD + c);
                cpa16(&vs[r * DP + c], vp + (size_t)r * DHEAD + c);
            }
            CP_COMMIT();
        }
    }

    float oacc[16][4];
#pragma unroll
    for (int in = 0; in < 16; in++)
#pragma unroll
        for (int j = 0; j < 4; j++) oacc[in][j] = 0.f;
    float m_i[2] = {-INFINITY, -INFINITY};
    float l_i[2] = {0.f, 0.f};

    const int rlo = qt * ABR + w * 16 + g;

    for (int kt = 0; kt < ktmax; kt++) {
        if (kt + 2 < ktmax) {
            int s = (kt + 2) % NBUF;
            float* ks = fsm + s * TILEF;
            float* vs = fsm + (NBUF + s) * TILEF;
            const float* kp = Kb + (size_t)(kt + 2) * ABC * DHEAD;
            const float* vp = Vb + (size_t)(kt + 2) * ABC * DHEAD;
#pragma unroll
            for (int p = 0; p < 8; p++) {
                int idx = tid + p * 256;
                int r = idx >> 5;
                int c = (idx & 31) << 2;
                cpa16(&ks[r * DP + c], kp + (size_t)r * DHEAD + c);
                cpa16(&vs[r * DP + c], vp + (size_t)r * DHEAD + c);
            }
            CP_COMMIT();
            CP_WAIT2();
        } else if (kt + 1 < ktmax) {
            CP_WAIT1();
        } else {
            CP_WAIT0();
        }
        __syncthreads();

        const float* Ksc = fsm + (kt % NBUF) * TILEF;
        const float* Vsc = fsm + (NBUF + kt % NBUF) * TILEF;

        // S = Q @ K^T  (warp: 16 x 64; 8 n-atoms); K frags = 1 LDS.64 each
        float sacc[8][4];
#pragma unroll
        for (int in = 0; in < 8; in++)
#pragma unroll
            for (int j = 0; j < 4; j++) sacc[in][j] = 0.f;

#pragma unroll
        for (int ik = 0; ik < 16; ik++) {
#pragma unroll
            for (int in = 0; in < 8; in++) {
                int srow = in * 8 + g;
                int dcol = ik * 8 + 2 * tg;
                float2 kv = *(const float2*)&Ksc[srow * DP + dcol];
                uint32_t bf[2];
                bf[0] = __float_as_uint(kv.x);
                bf[1] = __float_as_uint(kv.y);
                mma_tf32(sacc[in], qf[ik], bf);
            }
        }

        // causal mask (band tiles only)
        if (kt >= KTF * qt) {
#pragma unroll
            for (int in = 0; in < 8; in++) {
                int cbase = kt * ABC + in * 8 + 2 * tg;
#pragma unroll
                for (int j = 0; j < 4; j++) {
                    int cg = cbase + (j & 1);
                    int rg = rlo + (j >> 1) * 8;
                    if (cg > rg) sacc[in][j] = -INFINITY;
                }
            }
        }

        // online softmax per owned row (rr=0: row g ; rr=1: row g+8)
        float alpha[2];
#pragma unroll
        for (int rr = 0; rr < 2; rr++) {
            float pm = -INFINITY;
#pragma unroll
            for (int in = 0; in < 8; in++) {
                pm = fmaxf(pm, sacc[in][2 * rr]);
                pm = fmaxf(pm, sacc[in][2 * rr + 1]);
            }
            pm = fmaxf(pm, __shfl_xor_sync(0xffffffffu, pm, 1));
            pm = fmaxf(pm, __shfl_xor_sync(0xffffffffu, pm, 2));
            float mnew = fmaxf(m_i[rr], pm);
            float ps = 0.f;
#pragma unroll
            for (int in = 0; in < 8; in++) {
                float e0 = __expf(sacc[in][2 * rr]     - mnew);
                float e1 = __expf(sacc[in][2 * rr + 1] - mnew);
                sacc[in][2 * rr] = e0;
                sacc[in][2 * rr + 1] = e1;
                ps += e0 + e1;
            }
            ps += __shfl_xor_sync(0xffffffffu, ps, 1);
            ps += __shfl_xor_sync(0xffffffffu, ps, 2);
            alpha[rr] = __expf(m_i[rr] - mnew);
            l_i[rr] = l_i[rr] * alpha[rr] + ps;
            m_i[rr] = mnew;
        }
#pragma unroll
        for (int in = 0; in < 16; in++) {
            oacc[in][0] *= alpha[0]; oacc[in][1] *= alpha[0];
            oacc[in][2] *= alpha[1]; oacc[in][3] *= alpha[1];
        }

        // O += P @ V  (P converted C-frag -> A-frag via shfl; raw fp32 bits)
#pragma unroll
        for (int ik = 0; ik < 8; ik++) {
            const int srcA = (lane & 28) | (tg >> 1);
            const int srcB = srcA + 2;
            const bool odd = (tg & 1) != 0;
            float e0 = __shfl_sync(0xffffffffu, sacc[ik][0], srcA);
            float e1 = __shfl_sync(0xffffffffu, sacc[ik][1], srcA);
            float e2 = __shfl_sync(0xffffffffu, sacc[ik][2], srcA);
            float e3 = __shfl_sync(0xffffffffu, sacc[ik][3], srcA);
            float f0 = __shfl_sync(0xffffffffu, sacc[ik][0], srcB);
            float f1 = __shfl_sync(0xffffffffu, sacc[ik][1], srcB);
            float f2 = __shfl_sync(0xffffffffu, sacc[ik][2], srcB);
            float f3 = __shfl_sync(0xffffffffu, sacc[ik][3], srcB);
            uint32_t af[4];
            af[0] = __float_as_uint(odd ? e1 : e0);   // P[g][tg]
            af[1] = __float_as_uint(odd ? e3 : e2);   // P[g+8][tg]
            af[2] = __float_as_uint(odd ? f1 : f0);   // P[g][tg+4]
            af[3] = __float_as_uint(odd ? f3 : f2);   // P[g+8][tg+4]
#pragma unroll
            for (int in = 0; in < 16; in++) {
                uint32_t bf[2];
                int krow = ik * 8 + tg;
                int dcol = in * 8 + g;
                bf[0] = __float_as_uint(Vsc[krow * DP + dcol]);
                bf[1] = __float_as_uint(Vsc[(krow + 4) * DP + dcol]);
                mma_tf32(oacc[in], af, bf);
            }
        }
        __syncthreads();   // all warps done with buffer kt%3 before refill
    }

    // epilogue: write O in [B,T,D] layout (fused permute; true d layout)
    float inv0 = 1.f / l_i[0];
    float inv1 = 1.f / l_i[1];
    {
        const int b = bh >> 4;
        const int h = bh & (NHEAD - 1);
        const int t0 = qt * ABR + w * 16 + g;
        float* O0 = Og + ((size_t)(b * TSEQ + t0)     ) * DMOD + h * DHEAD;
        float* O1 = Og + ((size_t)(b * TSEQ + t0 + 8) ) * DMOD + h * DHEAD;
#pragma unroll
        for (int in = 0; in < 16; in++) {
            int c = in * 8 + 2 * tg;
            *(float2*)(O0 + c) =
                make_float2(oacc[in][0] * inv0, oacc[in][1] * inv0);
            *(float2*)(O1 + c) =
                make_float2(oacc[in][2] * inv1, oacc[in][3] * inv1);
        }
    }
}

// ---------------------------------------------------------------------------
// Host launcher
// ---------------------------------------------------------------------------
extern "C" void kernel_launch(void* const* d_in, const int* in_sizes, int n_in,
                              void* d_out, int out_size)
{
    const float* x     = (const float*)d_in[0];
    const float* Wqkv  = (const float*)d_in[1];
    const float* Wout  = (const float*)d_in[2];
    const float* Wgate = (const float*)d_in[3];
    const float* bgate = (const float*)d_in[4];
    float* out = (float*)d_out;

    float *qkv, *q, *k, *v, *o, *g, *xr, *wqkvr, *wgater, *woutr;
    float2* rtab;
    cudaGetSymbolAddress((void**)&qkv,    g_qkv);
    cudaGetSymbolAddress((void**)&q,      g_q);
    cudaGetSymbolAddress((void**)&k,      g_k);
    cudaGetSymbolAddress((void**)&v,      g_v);
    cudaGetSymbolAddress((void**)&o,      g_o);
    cudaGetSymbolAddress((void**)&g,      g_g);
    cudaGetSymbolAddress((void**)&xr,     g_xr);
    cudaGetSymbolAddress((void**)&wqkvr,  g_wqkvr);
    cudaGetSymbolAddress((void**)&wgater, g_wgater);
    cudaGetSymbolAddress((void**)&woutr,  g_woutr);
    cudaGetSymbolAddress((void**)&rtab,   g_rope);

    // 0) pre-pass (3 launches -> QKV GEMM is launch #4 for ncu)
    pre_x_rope_kernel<<<(RNX + RNR + 255) / 256, 256>>>(x, xr, rtab);
    pre_wqkv_kernel<<<(RN2 + 255) / 256, 256>>>(Wqkv, wqkvr);
    pre_wgo_kernel<<<(2 * RN3 + 255) / 256, 256>>>(Wgate, wgater, Wout, woutr);

    size_t gemm_smem = (size_t)GEMM_SMEM_FLOATS * sizeof(float);
    cudaFuncSetAttribute(mm_tf32_kernel,
                         cudaFuncAttributeMaxDynamicSharedMemorySize, (int)gemm_smem);

    // 1) QKV GEMM (launch #4 -> ncu target)
    mm_tf32_kernel<<<dim3(QKVN / BN, MROWS / BM), GTHR, gemm_smem>>>(
        xr, wqkvr, qkv, MROWS, QKVN, DMOD, 0, nullptr, nullptr);

    // 2) RMSNorm + RoPE + permute (launch #5)
    norm_rope_kernel<<<BATCH * NHEAD * TSEQ, 128>>>(qkv, rtab, q, k, v);

    // 3) Flash attention (launch #6)
    size_t fl_smem = (size_t)FSM_FLOATS * sizeof(float);
    cudaFuncSetAttribute(flash_mma_kernel,
                         cudaFuncAttributeMaxDynamicSharedMemorySize, (int)fl_smem);
    flash_mma_kernel<<<dim3(TSEQ / ABR, BATCH * NHEAD), 256, fl_smem>>>(q, k, v, o);

    // 4) gate GEMM with fused sigmoid * attn epilogue (launch #7)
    mm_tf32_kernel<<<dim3(DMOD / BN, MROWS / BM), GTHR, gemm_smem>>>(
        xr, wgater, g, MROWS, DMOD, DMOD, 1, bgate, o);

    // 5) output GEMM (launch #8; A = g is k-permuted)
    mm_tf32_kernel<<<dim3(DMOD / BN, MROWS / BM), GTHR, gemm_smem>>>(
        g, woutr, out, MROWS, DMOD, DMOD, 0, nullptr, nullptr);
}